// round 7
// baseline (speedup 1.0000x reference)
#include <cuda_runtime.h>
#include <cuda_bf16.h>
#include <math.h>
#include <stdint.h>

#define BB 2
#define LL 1024
#define DIM 512
#define DSTATE 64
#define DCONV 4
#define DIN 2048
#define DTRANK 32
#define XDBL 160            // DT_RANK + 2*D_STATE
#define ROWS 2048           // B*L

// ---------------- scratch (device globals; no allocs allowed) ----------------
static __device__ __align__(16) float g_xz  [ROWS * 2 * DIN];
static __device__ __align__(16) float g_u   [ROWS * DIN];
static __device__ __align__(16) float g_xdbl[ROWS * XDBL];
static __device__ __align__(16) float g_dt  [ROWS * DIN];
static __device__ __align__(16) float g_x2  [ROWS * DIM];
static __device__ __align__(16) float g_part[4 * ROWS * XDBL];                   // split-K partials (x_proj)
static __device__ __align__(16) __nv_bfloat16 g_actb [ROWS * 6144];              // A' split-bf16
static __device__ __align__(16) __nv_bfloat16 g_actb2[ROWS * 6144];              // A' (2nd, for MLP)
static __device__ __align__(16) __nv_bfloat16 g_wb  [4096 * 1536 + 512 * 6144]; // W' split-bf16

// ---------------- math helpers ----------------
__device__ __forceinline__ float sigmoidf_(float x) { return __fdividef(1.f, 1.f + __expf(-x)); }
__device__ __forceinline__ float softplusf_(float x){ return x > 20.f ? x : log1pf(__expf(x)); }
__device__ __forceinline__ float geluf_(float x)    { return 0.5f * x * (1.f + erff(x * 0.70710678118654752f)); }
__device__ __forceinline__ float ex2_(float x) {
    float r; asm("ex2.approx.f32 %0, %1;" : "=f"(r) : "f"(x)); return r;
}

__device__ __forceinline__ void split_store3(__nv_bfloat16* base, size_t rb, int k, int K, float v) {
    __nv_bfloat16 hi = __float2bfloat16(v);
    __nv_bfloat16 lo = __float2bfloat16(v - __bfloat162float(hi));
    base[rb + k] = hi; base[rb + K + k] = lo; base[rb + 2 * K + k] = hi;
}

// ---------------- PTX helpers (baseline ISA only: sm_80+, valid on sm_103) ----------------
__device__ __forceinline__ uint32_t smem_u32(const void* p) {
    uint32_t a;
    asm("{ .reg .u64 t; cvta.to.shared.u64 t, %1; cvt.u32.u64 %0, t; }" : "=r"(a) : "l"(p));
    return a;
}
__device__ __forceinline__ void cp16(uint32_t dst, const void* src, int srcsize) {
    asm volatile("cp.async.cg.shared.global [%0], [%1], 16, %2;" :: "r"(dst), "l"(src), "r"(srcsize) : "memory");
}
#define CP_COMMIT() asm volatile("cp.async.commit_group;" ::: "memory")
#define CP_WAIT2()  asm volatile("cp.async.wait_group 2;" ::: "memory")

__device__ __forceinline__ void ldsm4(uint32_t& r0, uint32_t& r1, uint32_t& r2, uint32_t& r3, uint32_t addr) {
    asm volatile("ldmatrix.sync.aligned.m8n8.x4.shared.b16 {%0,%1,%2,%3}, [%4];"
                 : "=r"(r0), "=r"(r1), "=r"(r2), "=r"(r3) : "r"(addr));
}
__device__ __forceinline__ void mma16816(float* c, const uint32_t* a, const uint32_t* b) {
    asm volatile("mma.sync.aligned.m16n8k16.row.col.f32.bf16.bf16.f32 "
                 "{%0,%1,%2,%3}, {%4,%5,%6,%7}, {%8,%9}, {%0,%1,%2,%3};"
                 : "+f"(c[0]), "+f"(c[1]), "+f"(c[2]), "+f"(c[3])
                 : "r"(a[0]), "r"(a[1]), "r"(a[2]), "r"(a[3]), "r"(b[0]), "r"(b[1]));
}

// ---------------- LayerNorm (writes split-bf16 3-plane directly, K=512 -> K3p=1536) ----------------
__global__ void __launch_bounds__(128)
ln_kernel(const float* __restrict__ x, const float* __restrict__ g,
          const float* __restrict__ b, __nv_bfloat16* __restrict__ outb, float eps)
{
    int row = blockIdx.x;
    const float* xr = x + (size_t)row * DIM;
    float v[4];
    float s = 0.f;
#pragma unroll
    for (int i = 0; i < 4; i++) { v[i] = xr[threadIdx.x + i * 128]; s += v[i]; }
    __shared__ float red[8];
#pragma unroll
    for (int o = 16; o > 0; o >>= 1) s += __shfl_xor_sync(0xffffffffu, s, o);
    if ((threadIdx.x & 31) == 0) red[threadIdx.x >> 5] = s;
    __syncthreads();
    float mean = (red[0] + red[1] + red[2] + red[3]) * (1.f / DIM);
    float s2 = 0.f;
#pragma unroll
    for (int i = 0; i < 4; i++) { float d = v[i] - mean; s2 += d * d; }
#pragma unroll
    for (int o = 16; o > 0; o >>= 1) s2 += __shfl_xor_sync(0xffffffffu, s2, o);
    if ((threadIdx.x & 31) == 0) red[4 + (threadIdx.x >> 5)] = s2;
    __syncthreads();
    float var = (red[4] + red[5] + red[6] + red[7]) * (1.f / DIM);
    float rstd = rsqrtf(var + eps);
    size_t rb = (size_t)row * 1536;
#pragma unroll
    for (int i = 0; i < 4; i++) {
        int c = threadIdx.x + i * 128;
        float o = (v[i] - mean) * rstd * g[c] + b[c];
        split_store3(outb, rb, c, DIM, o);
    }
}

// ---------------- fp32 -> split-bf16 (3-plane) conversion ----------------
__global__ void __launch_bounds__(256)
cvt_split(const float* __restrict__ src, int lda, int K, int K3p, int rows,
          __nv_bfloat16* __restrict__ dst, int mode)
{
    int i = blockIdx.x * 256 + threadIdx.x;
    if (i >= rows * K) return;
    int r = i / K, k = i - r * K;
    float a = src[(size_t)r * lda + k];
    __nv_bfloat16 hi = __float2bfloat16(a);
    __nv_bfloat16 lo = __float2bfloat16(a - __bfloat162float(hi));
    __nv_bfloat16* dr = dst + (size_t)r * K3p;
    if (mode == 0) { dr[k] = hi; dr[K + k] = lo;  dr[2 * K + k] = hi; }
    else           { dr[k] = hi; dr[K + k] = hi;  dr[2 * K + k] = lo; }
}

__global__ void __launch_bounds__(256)
pad_zero(__nv_bfloat16* __restrict__ dst, int K3p, int k0, int rows)
{
    int pad = K3p - k0;
    int i = blockIdx.x * 256 + threadIdx.x;
    if (i >= rows * pad) return;
    int r = i / pad, k = i - r * pad;
    dst[(size_t)r * K3p + k0 + k] = __float2bfloat16(0.f);
}

// ---------------- HMMA GEMM: C[M,N] = A'[M,K3] @ W'[N,K3]^T ----------------
// BM=128, BN in {64,128}, BK=32 bf16, 4-stage cp.async pipeline, 1 barrier/chunk.
// 256 threads, warp grid 4(m)x2(n); warp tile 32 x (BN/2).
// EPI: 0 none, 1 bias+softplus, 2 +resid, 4 bias+resid, 5 bias+gelu -> split-bf16 g_actb2
#define APITCH 80                       // 32 bf16 (64B) + 16B pad
template<int BN, int EPI>
__global__ void __launch_bounds__(256, 2)
hmma_gemm(const __nv_bfloat16* __restrict__ A, const __nv_bfloat16* __restrict__ W,
          float* __restrict__ C, int N, int K3, int Ksl, size_t partStride,
          const float* __restrict__ bias, const float* __restrict__ resid)
{
    constexpr int STAGE = 128 * APITCH + BN * APITCH;
    constexpr int NTG = BN / 16;          // nt groups per warp (8 cols each)
    extern __shared__ __align__(16) char dsm[];

    const int tid = threadIdx.x;
    const int lane = tid & 31, wid = tid >> 5;
    const int warpM = (wid & 3) * 32;               // 4 warps along M
    const int warpN = (wid >> 2) * (BN / 2);        // 2 warps along N
    const int m0 = blockIdx.y * 128;
    const int n0 = blockIdx.x * BN;
    const int koff = blockIdx.z * Ksl;
    const int NC = Ksl / 32;
    C += (size_t)blockIdx.z * partStride;

    const uint32_t sbase = smem_u32(dsm);
    uint32_t aB[4], bB[4];
#pragma unroll
    for (int s = 0; s < 4; s++) { aB[s] = sbase + s * STAGE; bB[s] = aB[s] + 128 * APITCH; }

    const int lr = tid >> 2, lseg = tid & 3;
    const uint32_t aLdOff = (uint32_t)((warpM + (lane & 15)) * APITCH + (lane >> 4) * 16);
    const uint32_t bLdOff = (uint32_t)((warpN + (lane & 7)) * APITCH + (lane >> 3) * 16);

    float acc[2][NTG][4];
#pragma unroll
    for (int i = 0; i < 2; i++)
#pragma unroll
        for (int j = 0; j < NTG; j++)
#pragma unroll
            for (int q = 0; q < 4; q++) acc[i][j][q] = 0.f;

    auto load_chunk = [&](int buf, int c) {
        const __nv_bfloat16* asrc = A + (size_t)(m0 + lr) * K3 + koff + c * 32 + lseg * 8;
        cp16(aB[buf] + (uint32_t)(lr * APITCH + lseg * 16), asrc, 16);
        cp16(aB[buf] + (uint32_t)((lr + 64) * APITCH + lseg * 16), asrc + (size_t)64 * K3, 16);
        if (BN == 128) {
            int brow = n0 + lr;
            bool bv0 = (brow < N), bv1 = (brow + 64 < N);
            const __nv_bfloat16* bsrc = W + (size_t)(bv0 ? brow : 0) * K3 + koff + c * 32 + lseg * 8;
            cp16(bB[buf] + (uint32_t)(lr * APITCH + lseg * 16), bsrc, bv0 ? 16 : 0);
            const __nv_bfloat16* bsrc1 = W + (size_t)(bv1 ? (brow + 64) : 0) * K3 + koff + c * 32 + lseg * 8;
            cp16(bB[buf] + (uint32_t)((lr + 64) * APITCH + lseg * 16), bsrc1, bv1 ? 16 : 0);
        } else {
            if (lr < 64) {
                int brow = n0 + lr;
                bool bv = (brow < N);
                const __nv_bfloat16* bsrc = W + (size_t)(bv ? brow : 0) * K3 + koff + c * 32 + lseg * 8;
                cp16(bB[buf] + (uint32_t)(lr * APITCH + lseg * 16), bsrc, bv ? 16 : 0);
            }
        }
    };

    const int pf = NC < 3 ? NC : 3;
    for (int p = 0; p < pf; p++) { load_chunk(p, p); CP_COMMIT(); }

    for (int c = 0; c < NC; c++) {
        CP_WAIT2();
        __syncthreads();
        if (c + 3 < NC) { load_chunk((c + 3) & 3, c + 3); CP_COMMIT(); }
        const int buf = c & 3;

        uint32_t aF[2][2][4];   // [mt][kh][4]
#pragma unroll
        for (int mt = 0; mt < 2; mt++)
#pragma unroll
            for (int kh = 0; kh < 2; kh++)
                ldsm4(aF[mt][kh][0], aF[mt][kh][1], aF[mt][kh][2], aF[mt][kh][3],
                      aB[buf] + aLdOff + (uint32_t)(mt * 16 * APITCH + kh * 32));
#pragma unroll
        for (int half = 0; half < NTG / 4; half++) {
            uint32_t bF[4][4];
#pragma unroll
            for (int j = 0; j < 4; j++)
                ldsm4(bF[j][0], bF[j][1], bF[j][2], bF[j][3],
                      bB[buf] + bLdOff + (uint32_t)((half * 4 + j) * 8 * APITCH));
#pragma unroll
            for (int kh = 0; kh < 2; kh++)
#pragma unroll
                for (int mt = 0; mt < 2; mt++)
#pragma unroll
                    for (int j = 0; j < 4; j++)
                        mma16816(acc[mt][half * 4 + j], aF[mt][kh], &bF[j][kh * 2]);
        }
    }

    // ---- epilogue ----
#pragma unroll
    for (int mt = 0; mt < 2; mt++) {
        int row = m0 + warpM + mt * 16 + (lane >> 2);
#pragma unroll
        for (int nt = 0; nt < NTG; nt++) {
            int col = n0 + warpN + nt * 8 + 2 * (lane & 3);
            if (col < N) {
                float v0 = acc[mt][nt][0], v1 = acc[mt][nt][1];
                float v2 = acc[mt][nt][2], v3 = acc[mt][nt][3];
                if (EPI == 1) {
                    float b0 = bias[col], b1 = bias[col + 1];
                    v0 = softplusf_(v0 + b0); v1 = softplusf_(v1 + b1);
                    v2 = softplusf_(v2 + b0); v3 = softplusf_(v3 + b1);
                } else if (EPI == 5 || EPI == 4) {
                    float b0 = bias[col], b1 = bias[col + 1];
                    v0 += b0; v1 += b1; v2 += b0; v3 += b1;
                    if (EPI == 5) { v0 = geluf_(v0); v1 = geluf_(v1); v2 = geluf_(v2); v3 = geluf_(v3); }
                }
                size_t i0 = (size_t)row * N + col;
                size_t i1 = (size_t)(row + 8) * N + col;
                if (EPI == 2 || EPI == 4) {
                    float2 r0 = *(const float2*)&resid[i0];
                    float2 r1 = *(const float2*)&resid[i1];
                    v0 += r0.x; v1 += r0.y; v2 += r1.x; v3 += r1.y;
                }
                if (EPI == 5) {
                    size_t rb0 = (size_t)row * 6144;
                    size_t rb1 = (size_t)(row + 8) * 6144;
                    split_store3(g_actb2, rb0, col,     2048, v0);
                    split_store3(g_actb2, rb0, col + 1, 2048, v1);
                    split_store3(g_actb2, rb1, col,     2048, v2);
                    split_store3(g_actb2, rb1, col + 1, 2048, v3);
                } else {
                    *(float2*)&C[i0] = make_float2(v0, v1);
                    *(float2*)&C[i1] = make_float2(v2, v3);
                }
            }
        }
    }
}

// ---------------- split-K reduce (x_proj only) ----------------
__global__ void __launch_bounds__(256)
reduce_kernel(const float* __restrict__ part, float* __restrict__ out,
              int total4, int slices, size_t partStride)
{
    int i = blockIdx.x * 256 + threadIdx.x;
    if (i >= total4) return;
    size_t e = (size_t)i * 4;
    float4 acc = *(const float4*)(part + e);
    for (int s = 1; s < slices; s++) {
        float4 v = *(const float4*)(part + (size_t)s * partStride + e);
        acc.x += v.x; acc.y += v.y; acc.z += v.z; acc.w += v.w;
    }
    *(float4*)(out + e) = acc;
}

// ---------------- depthwise causal conv (D_CONV=4) + SiLU; writes u fp32 + split-bf16 ----------------
__global__ void __launch_bounds__(256)
conv_silu_kernel(const float* __restrict__ cw, const float* __restrict__ cb)
{
    int gid = blockIdx.x * 256 + threadIdx.x;   // over ROWS*DIN
    int d = gid & (DIN - 1);
    int row = gid >> 11;
    int t = row & (LL - 1);
    float acc = cb[d];
    const float* base = g_xz + (size_t)row * (2 * DIN) + d;
#pragma unroll
    for (int k = 0; k < DCONV; k++) {
        int off = k - (DCONV - 1);
        if (t + off >= 0)
            acc = fmaf(cw[d * DCONV + k], base[(long)off * (2 * DIN)], acc);
    }
    float s = acc * sigmoidf_(acc);
    g_u[gid] = s;
    split_store3(g_actb, (size_t)row * 6144, d, DIN, s);
}

// ---------------- selective scan v2: warp per (b,d) channel ----------------
#define GD 8
#define CT 32

__global__ void __launch_bounds__(256)
scan_kernel(const float* __restrict__ A_log, const float* __restrict__ Dw)
{
    __shared__ float sB[CT][DSTATE];
    __shared__ float sC[CT][DSTATE];
    __shared__ float sdt[CT][GD];
    __shared__ float su [CT][GD];
    __shared__ float sz [CT][GD];
    __shared__ float sp [GD][CT][33];

    const int tid = threadIdx.x;
    const int w = tid >> 5, lane = tid & 31;
    const int b = blockIdx.y;
    const int d0 = blockIdx.x * GD;
    const int d = d0 + w;

    const float L2E = 1.44269504f;
    const float a0 = -__expf(A_log[d * DSTATE + 2 * lane])     * L2E;
    const float a1 = -__expf(A_log[d * DSTATE + 2 * lane + 1]) * L2E;
    const float Dd = Dw[d];
    float h0 = 0.f, h1 = 0.f;

    const float* xdbl_b = g_xdbl + (size_t)b * LL * XDBL;
    const float* dt_b = g_dt + (size_t)b * LL * DIN + d0;
    const float* u_b  = g_u  + (size_t)b * LL * DIN + d0;
    const float* z_b  = g_xz + (size_t)b * LL * (2 * DIN) + DIN + d0;

    for (int t0 = 0; t0 < LL; t0 += CT) {
        __syncthreads();
#pragma unroll
        for (int r = 0; r < (CT * DSTATE) / 256; r++) {
            int e = tid + r * 256;
            int tt = e >> 6, n = e & 63;
            const float* src = xdbl_b + (size_t)(t0 + tt) * XDBL + DTRANK;
            sB[tt][n] = src[n];
            sC[tt][n] = src[DSTATE + n];
        }
        {
            int tt = tid >> 3, dd = tid & 7;
            sdt[tt][dd] = dt_b[(size_t)(t0 + tt) * DIN + dd];
            su [tt][dd] = u_b [(size_t)(t0 + tt) * DIN + dd];
            sz [tt][dd] = z_b [(size_t)(t0 + tt) * (2 * DIN) + dd];
        }
        __syncthreads();
#pragma unroll 8
        for (int tt = 0; tt < CT; tt++) {
            float dtv = sdt[tt][w], uv = su[tt][w];
            float2 Bv = *(const float2*)&sB[tt][2 * lane];
            float2 Cv = *(const float2*)&sC[tt][2 * lane];
            float dA0 = ex2_(dtv * a0);
            float dA1 = ex2_(dtv * a1);
            float du = dtv * uv;
            h0 = fmaf(dA0, h0, du * Bv.x);
            h1 = fmaf(dA1, h1, du * Bv.y);
            sp[w][tt][lane] = fmaf(h1, Cv.y, h0 * Cv.x);
        }
        __syncwarp();
        {
            const float* pr = &sp[w][lane][0];
            float sum = 0.f;
#pragma unroll
            for (int i = 0; i < 32; i++) sum += pr[i];
            float uvv = su[lane][w];
            float zvv = sz[lane][w];
            float yv = fmaf(uvv, Dd, sum);
            float o = yv * (zvv * sigmoidf_(zvv));
            split_store3(g_actb, (size_t)(b * LL + t0 + lane) * 6144, d, DIN, o);
        }
    }
}

// ---------------- launch ----------------
static inline int cdiv(int a, int b) { return (a + b - 1) / b; }

extern "C" void kernel_launch(void* const* d_in, const int* in_sizes, int n_in,
                              void* d_out, int out_size)
{
    const float* x         = (const float*)d_in[0];
    const float* ln1_g     = (const float*)d_in[1];
    const float* ln1_b     = (const float*)d_in[2];
    const float* in_proj_w = (const float*)d_in[3];
    const float* conv_w    = (const float*)d_in[4];
    const float* conv_b    = (const float*)d_in[5];
    const float* x_proj_w  = (const float*)d_in[6];
    const float* dt_w      = (const float*)d_in[7];
    const float* dt_b      = (const float*)d_in[8];
    const float* A_log     = (const float*)d_in[9];
    const float* D         = (const float*)d_in[10];
    const float* out_proj_w= (const float*)d_in[11];
    const float* ln2_g     = (const float*)d_in[12];
    const float* ln2_b     = (const float*)d_in[13];
    const float* w1        = (const float*)d_in[14];
    const float* b1        = (const float*)d_in[15];
    const float* w2        = (const float*)d_in[16];
    const float* b2        = (const float*)d_in[17];
    float* out = (float*)d_out;

    float *xz, *u, *xdbl, *dt, *x2, *part;
    __nv_bfloat16 *actb, *actb2, *wb;
    cudaGetSymbolAddress((void**)&xz,   g_xz);
    cudaGetSymbolAddress((void**)&u,    g_u);
    cudaGetSymbolAddress((void**)&xdbl, g_xdbl);
    cudaGetSymbolAddress((void**)&dt,   g_dt);
    cudaGetSymbolAddress((void**)&x2,   g_x2);
    cudaGetSymbolAddress((void**)&part, g_part);
    cudaGetSymbolAddress((void**)&actb, g_actb);
    cudaGetSymbolAddress((void**)&actb2,g_actb2);
    cudaGetSymbolAddress((void**)&wb,   g_wb);

    const int SM64  = 4 * (128 * APITCH + 64 * APITCH);    // 61440
    const int SM128 = 4 * (128 * APITCH + 128 * APITCH);   // 81920
    cudaFuncSetAttribute(hmma_gemm<64, 0>,  cudaFuncAttributeMaxDynamicSharedMemorySize, SM64);
    cudaFuncSetAttribute(hmma_gemm<64, 2>,  cudaFuncAttributeMaxDynamicSharedMemorySize, SM64);
    cudaFuncSetAttribute(hmma_gemm<64, 4>,  cudaFuncAttributeMaxDynamicSharedMemorySize, SM64);
    cudaFuncSetAttribute(hmma_gemm<128, 0>, cudaFuncAttributeMaxDynamicSharedMemorySize, SM128);
    cudaFuncSetAttribute(hmma_gemm<128, 1>, cudaFuncAttributeMaxDynamicSharedMemorySize, SM128);
    cudaFuncSetAttribute(hmma_gemm<128, 5>, cudaFuncAttributeMaxDynamicSharedMemorySize, SM128);

    // 1. LN1 -> actb (split-bf16, K3p=1536)
    ln_kernel<<<ROWS, 128>>>(x, ln1_g, ln1_b, actb, 1e-5f);

    // 2. in_proj: xz = y @ in_proj_w^T  [2048 x 4096], K3=1536
    cvt_split<<<cdiv(4096 * DIM, 256), 256>>>(in_proj_w, DIM, DIM, 1536, 4096, wb, 1);
    hmma_gemm<128, 0><<<dim3(32, 16, 1), 256, SM128>>>(actb, wb, xz, 2 * DIN, 1536, 1536, 0, nullptr, nullptr);

    // 3. causal conv + silu -> u (fp32) + actb (split-bf16, K3p=6144)
    conv_silu_kernel<<<(ROWS * DIN) / 256, 256>>>(conv_w, conv_b);

    // 4. x_proj: xdbl = u @ x_proj_w^T  [2048 x 160], K3=6144, split-K=4
    cvt_split<<<cdiv(XDBL * DIN, 256), 256>>>(x_proj_w, DIN, DIN, 6144, XDBL, wb, 1);
    hmma_gemm<64, 0><<<dim3(3, 16, 4), 256, SM64>>>(actb, wb, part, XDBL, 6144, 1536,
                                                    (size_t)ROWS * XDBL, nullptr, nullptr);
    reduce_kernel<<<(ROWS * XDBL / 4 + 255) / 256, 256>>>(part, xdbl, ROWS * XDBL / 4, 4,
                                                          (size_t)ROWS * XDBL);

    // 5. dt = softplus(xdbl[:, :32] @ dt_w^T + dt_b)  [2048 x 2048], K3=96 pad 128
    cvt_split<<<cdiv(ROWS * DTRANK, 256), 256>>>(xdbl, XDBL, DTRANK, 128, ROWS, actb2, 0);
    cvt_split<<<cdiv(DIN * DTRANK, 256), 256>>>(dt_w, DTRANK, DTRANK, 128, DIN, wb, 1);
    pad_zero<<<cdiv(ROWS * 32, 256), 256>>>(actb2, 128, 96, ROWS);
    pad_zero<<<cdiv(DIN * 32, 256), 256>>>(wb, 128, 96, DIN);
    hmma_gemm<128, 1><<<dim3(16, 16, 1), 256, SM128>>>(actb2, wb, dt, DIN, 128, 128, 0, dt_b, nullptr);

    // 6. selective scan -> actb (split-bf16, K3p=6144)
    scan_kernel<<<dim3(DIN / GD, BB), 256>>>(A_log, D);

    // 7. out_proj (fused resid): x2 = x + ys @ out_proj_w^T  [2048 x 512], K3=6144
    cvt_split<<<cdiv(DIM * DIN, 256), 256>>>(out_proj_w, DIN, DIN, 6144, DIM, wb, 1);
    hmma_gemm<64, 2><<<dim3(8, 16, 1), 256, SM64>>>(actb, wb, x2, DIM, 6144, 6144, 0, nullptr, x);

    // 8. LN2 -> actb (split-bf16, K3p=1536)
    ln_kernel<<<ROWS, 128>>>(x2, ln2_g, ln2_b, actb, 1e-6f);

    // 9. h1 = gelu(y2 @ w1^T + b1) -> actb2 (split-bf16, K3p=6144)  [2048 x 2048], K3=1536
    cvt_split<<<cdiv(4 * DIM * DIM, 256), 256>>>(w1, DIM, DIM, 1536, 4 * DIM, wb, 1);
    hmma_gemm<128, 5><<<dim3(16, 16, 1), 256, SM128>>>(actb, wb, nullptr, 4 * DIM, 1536, 1536, 0, b1, nullptr);

    // 10. out (fused bias+resid): out = x2 + h1 @ w2^T + b2  [2048 x 512], K3=6144
    cvt_split<<<cdiv(DIM * DIN, 256), 256>>>(w2, DIN, DIN, 6144, DIM, wb, 1);
    hmma_gemm<64, 4><<<dim3(8, 16, 1), 256, SM64>>>(actb2, wb, out, DIM, 6144, 6144, 0, b2, x2);
}

// round 8
// speedup vs baseline: 1.0037x; 1.0037x over previous
#include <cuda_runtime.h>
#include <cuda_bf16.h>
#include <math.h>
#include <stdint.h>

#define BB 2
#define LL 1024
#define DIM 512
#define DSTATE 64
#define DCONV 4
#define DIN 2048
#define DTRANK 32
#define XDBL 160            // DT_RANK + 2*D_STATE
#define ROWS 2048           // B*L

// ---------------- scratch (device globals; no allocs allowed) ----------------
static __device__ __align__(16) float g_xz  [ROWS * 2 * DIN];
static __device__ __align__(16) float g_u   [ROWS * DIN];
static __device__ __align__(16) float g_xdbl[ROWS * XDBL];
static __device__ __align__(16) float g_dt  [ROWS * DIN];
static __device__ __align__(16) float g_x2  [ROWS * DIM];
static __device__ __align__(16) float g_part[4 * ROWS * XDBL];                   // split-K partials (x_proj)
static __device__ __align__(16) __nv_bfloat16 g_actb [ROWS * 6144];              // A' split-bf16
static __device__ __align__(16) __nv_bfloat16 g_actb2[ROWS * 6144];              // A' (2nd, for MLP)
static __device__ __align__(16) __nv_bfloat16 g_wb  [4096 * 1536 + 512 * 6144]; // W' split-bf16

// ---------------- math helpers ----------------
__device__ __forceinline__ float sigmoidf_(float x) { return __fdividef(1.f, 1.f + __expf(-x)); }
__device__ __forceinline__ float softplusf_(float x){ return x > 20.f ? x : log1pf(__expf(x)); }
__device__ __forceinline__ float geluf_(float x)    { return 0.5f * x * (1.f + erff(x * 0.70710678118654752f)); }
__device__ __forceinline__ float ex2_(float x) {
    float r; asm("ex2.approx.f32 %0, %1;" : "=f"(r) : "f"(x)); return r;
}

__device__ __forceinline__ void split_store3(__nv_bfloat16* base, size_t rb, int k, int K, float v) {
    __nv_bfloat16 hi = __float2bfloat16(v);
    __nv_bfloat16 lo = __float2bfloat16(v - __bfloat162float(hi));
    base[rb + k] = hi; base[rb + K + k] = lo; base[rb + 2 * K + k] = hi;
}

// ---------------- PTX helpers (baseline ISA only: sm_80+, valid on sm_103) ----------------
__device__ __forceinline__ uint32_t smem_u32(const void* p) {
    uint32_t a;
    asm("{ .reg .u64 t; cvta.to.shared.u64 t, %1; cvt.u32.u64 %0, t; }" : "=r"(a) : "l"(p));
    return a;
}
__device__ __forceinline__ void cp16(uint32_t dst, const void* src, int srcsize) {
    asm volatile("cp.async.cg.shared.global [%0], [%1], 16, %2;" :: "r"(dst), "l"(src), "r"(srcsize) : "memory");
}
#define CP_COMMIT() asm volatile("cp.async.commit_group;" ::: "memory")
#define CP_WAIT2()  asm volatile("cp.async.wait_group 2;" ::: "memory")

__device__ __forceinline__ void ldsm4(uint32_t& r0, uint32_t& r1, uint32_t& r2, uint32_t& r3, uint32_t addr) {
    asm volatile("ldmatrix.sync.aligned.m8n8.x4.shared.b16 {%0,%1,%2,%3}, [%4];"
                 : "=r"(r0), "=r"(r1), "=r"(r2), "=r"(r3) : "r"(addr));
}
__device__ __forceinline__ void mma16816(float* c, const uint32_t* a, const uint32_t* b) {
    asm volatile("mma.sync.aligned.m16n8k16.row.col.f32.bf16.bf16.f32 "
                 "{%0,%1,%2,%3}, {%4,%5,%6,%7}, {%8,%9}, {%0,%1,%2,%3};"
                 : "+f"(c[0]), "+f"(c[1]), "+f"(c[2]), "+f"(c[3])
                 : "r"(a[0]), "r"(a[1]), "r"(a[2]), "r"(a[3]), "r"(b[0]), "r"(b[1]));
}

// ---------------- LayerNorm (writes split-bf16 3-plane directly, K=512 -> K3p=1536) ----------------
__global__ void __launch_bounds__(128)
ln_kernel(const float* __restrict__ x, const float* __restrict__ g,
          const float* __restrict__ b, __nv_bfloat16* __restrict__ outb, float eps)
{
    int row = blockIdx.x;
    const float* xr = x + (size_t)row * DIM;
    float v[4];
    float s = 0.f;
#pragma unroll
    for (int i = 0; i < 4; i++) { v[i] = xr[threadIdx.x + i * 128]; s += v[i]; }
    __shared__ float red[8];
#pragma unroll
    for (int o = 16; o > 0; o >>= 1) s += __shfl_xor_sync(0xffffffffu, s, o);
    if ((threadIdx.x & 31) == 0) red[threadIdx.x >> 5] = s;
    __syncthreads();
    float mean = (red[0] + red[1] + red[2] + red[3]) * (1.f / DIM);
    float s2 = 0.f;
#pragma unroll
    for (int i = 0; i < 4; i++) { float d = v[i] - mean; s2 += d * d; }
#pragma unroll
    for (int o = 16; o > 0; o >>= 1) s2 += __shfl_xor_sync(0xffffffffu, s2, o);
    if ((threadIdx.x & 31) == 0) red[4 + (threadIdx.x >> 5)] = s2;
    __syncthreads();
    float var = (red[4] + red[5] + red[6] + red[7]) * (1.f / DIM);
    float rstd = rsqrtf(var + eps);
    size_t rb = (size_t)row * 1536;
#pragma unroll
    for (int i = 0; i < 4; i++) {
        int c = threadIdx.x + i * 128;
        float o = (v[i] - mean) * rstd * g[c] + b[c];
        split_store3(outb, rb, c, DIM, o);
    }
}

// ---------------- fp32 -> split-bf16 (3-plane) conversion ----------------
__global__ void __launch_bounds__(256)
cvt_split(const float* __restrict__ src, int lda, int K, int K3p, int rows,
          __nv_bfloat16* __restrict__ dst, int mode)
{
    int i = blockIdx.x * 256 + threadIdx.x;
    if (i >= rows * K) return;
    int r = i / K, k = i - r * K;
    float a = src[(size_t)r * lda + k];
    __nv_bfloat16 hi = __float2bfloat16(a);
    __nv_bfloat16 lo = __float2bfloat16(a - __bfloat162float(hi));
    __nv_bfloat16* dr = dst + (size_t)r * K3p;
    if (mode == 0) { dr[k] = hi; dr[K + k] = lo;  dr[2 * K + k] = hi; }
    else           { dr[k] = hi; dr[K + k] = hi;  dr[2 * K + k] = lo; }
}

__global__ void __launch_bounds__(256)
pad_zero(__nv_bfloat16* __restrict__ dst, int K3p, int k0, int rows)
{
    int pad = K3p - k0;
    int i = blockIdx.x * 256 + threadIdx.x;
    if (i >= rows * pad) return;
    int r = i / pad, k = i - r * pad;
    dst[(size_t)r * K3p + k0 + k] = __float2bfloat16(0.f);
}

// ---------------- HMMA GEMM: C[M,N] = A'[M,K3] @ W'[N,K3]^T ----------------
// BM=128, BN=64, BK=32 bf16, 4-stage cp.async pipeline, 1 barrier/chunk.
// 256 threads, warp grid 4(m)x2(n), warp tile 32x32.
// EPI: 0 none, 1 bias+softplus, 2 +resid, 4 bias+resid, 5 bias+gelu -> split-bf16 g_actb2
#define APITCH 80                       // 32 bf16 (64B) + 16B pad
#define STAGE_BYTES (128 * APITCH + 64 * APITCH)   // 15360
#define SMEMSZ (4 * STAGE_BYTES)                    // 61440
template<int EPI>
__global__ void __launch_bounds__(256)
hmma_gemm(const __nv_bfloat16* __restrict__ A, const __nv_bfloat16* __restrict__ W,
          float* __restrict__ C, int N, int K3, int Ksl, size_t partStride,
          const float* __restrict__ bias, const float* __restrict__ resid)
{
    extern __shared__ __align__(16) char dsm[];

    const int tid = threadIdx.x;
    const int lane = tid & 31, wid = tid >> 5;
    const int warpM = (wid & 3) * 32;     // 4 warps along M
    const int warpN = (wid >> 2) * 32;    // 2 warps along N
    const int m0 = blockIdx.y * 128;
    const int n0 = blockIdx.x * 64;
    const int koff = blockIdx.z * Ksl;
    const int NC = Ksl / 32;
    C += (size_t)blockIdx.z * partStride;

    const uint32_t sbase = smem_u32(dsm);
    uint32_t aB[4], bB[4];
#pragma unroll
    for (int s = 0; s < 4; s++) { aB[s] = sbase + s * STAGE_BYTES; bB[s] = aB[s] + 128 * APITCH; }

    const int lr = tid >> 2, lseg = tid & 3;
    const uint32_t aLdOff = (uint32_t)((warpM + (lane & 15)) * APITCH + (lane >> 4) * 16);
    const uint32_t bLdOff = (uint32_t)((warpN + (lane & 7)) * APITCH + (lane >> 3) * 16);

    float acc[2][4][4];
#pragma unroll
    for (int i = 0; i < 2; i++)
#pragma unroll
        for (int j = 0; j < 4; j++)
#pragma unroll
            for (int q = 0; q < 4; q++) acc[i][j][q] = 0.f;

    auto load_chunk = [&](int buf, int c) {
        const __nv_bfloat16* asrc = A + (size_t)(m0 + lr) * K3 + koff + c * 32 + lseg * 8;
        cp16(aB[buf] + (uint32_t)(lr * APITCH + lseg * 16), asrc, 16);
        const __nv_bfloat16* asrc2 = asrc + (size_t)64 * K3;
        cp16(aB[buf] + (uint32_t)((lr + 64) * APITCH + lseg * 16), asrc2, 16);
        if (lr < 64) {
            int brow = n0 + lr;
            bool bv = (brow < N);
            const __nv_bfloat16* bsrc = W + (size_t)(bv ? brow : 0) * K3 + koff + c * 32 + lseg * 8;
            cp16(bB[buf] + (uint32_t)(lr * APITCH + lseg * 16), bsrc, bv ? 16 : 0);
        }
    };

    const int pf = NC < 3 ? NC : 3;
    for (int p = 0; p < pf; p++) { load_chunk(p, p); CP_COMMIT(); }

    for (int c = 0; c < NC; c++) {
        CP_WAIT2();
        __syncthreads();
        if (c + 3 < NC) { load_chunk((c + 3) & 3, c + 3); CP_COMMIT(); }
        const int buf = c & 3;

        uint32_t aF[2][2][4];   // [mt][kh][4]
#pragma unroll
        for (int mt = 0; mt < 2; mt++)
#pragma unroll
            for (int kh = 0; kh < 2; kh++)
                ldsm4(aF[mt][kh][0], aF[mt][kh][1], aF[mt][kh][2], aF[mt][kh][3],
                      aB[buf] + aLdOff + (uint32_t)(mt * 16 * APITCH + kh * 32));
        uint32_t bF[4][4];      // [nt][{b0h0,b1h0,b0h1,b1h1}]
#pragma unroll
        for (int nt = 0; nt < 4; nt++)
            ldsm4(bF[nt][0], bF[nt][1], bF[nt][2], bF[nt][3],
                  bB[buf] + bLdOff + (uint32_t)(nt * 8 * APITCH));
#pragma unroll
        for (int kh = 0; kh < 2; kh++)
#pragma unroll
            for (int mt = 0; mt < 2; mt++)
#pragma unroll
                for (int nt = 0; nt < 4; nt++)
                    mma16816(acc[mt][nt], aF[mt][kh], &bF[nt][kh * 2]);
    }

    // ---- epilogue ----
#pragma unroll
    for (int mt = 0; mt < 2; mt++) {
        int row = m0 + warpM + mt * 16 + (lane >> 2);
#pragma unroll
        for (int nt = 0; nt < 4; nt++) {
            int col = n0 + warpN + nt * 8 + 2 * (lane & 3);
            if (col < N) {
                float v0 = acc[mt][nt][0], v1 = acc[mt][nt][1];
                float v2 = acc[mt][nt][2], v3 = acc[mt][nt][3];
                if (EPI == 1) {
                    float b0 = bias[col], b1 = bias[col + 1];
                    v0 = softplusf_(v0 + b0); v1 = softplusf_(v1 + b1);
                    v2 = softplusf_(v2 + b0); v3 = softplusf_(v3 + b1);
                } else if (EPI == 5 || EPI == 4) {
                    float b0 = bias[col], b1 = bias[col + 1];
                    v0 += b0; v1 += b1; v2 += b0; v3 += b1;
                    if (EPI == 5) { v0 = geluf_(v0); v1 = geluf_(v1); v2 = geluf_(v2); v3 = geluf_(v3); }
                }
                size_t i0 = (size_t)row * N + col;
                size_t i1 = (size_t)(row + 8) * N + col;
                if (EPI == 2 || EPI == 4) {
                    float2 r0 = *(const float2*)&resid[i0];
                    float2 r1 = *(const float2*)&resid[i1];
                    v0 += r0.x; v1 += r0.y; v2 += r1.x; v3 += r1.y;
                }
                if (EPI == 5) {
                    size_t rb0 = (size_t)row * 6144;
                    size_t rb1 = (size_t)(row + 8) * 6144;
                    split_store3(g_actb2, rb0, col,     2048, v0);
                    split_store3(g_actb2, rb0, col + 1, 2048, v1);
                    split_store3(g_actb2, rb1, col,     2048, v2);
                    split_store3(g_actb2, rb1, col + 1, 2048, v3);
                } else {
                    *(float2*)&C[i0] = make_float2(v0, v1);
                    *(float2*)&C[i1] = make_float2(v2, v3);
                }
            }
        }
    }
}

// ---------------- split-K reduce (x_proj only) ----------------
__global__ void __launch_bounds__(256)
reduce_kernel(const float* __restrict__ part, float* __restrict__ out,
              int total4, int slices, size_t partStride)
{
    int i = blockIdx.x * 256 + threadIdx.x;
    if (i >= total4) return;
    size_t e = (size_t)i * 4;
    float4 acc = *(const float4*)(part + e);
    for (int s = 1; s < slices; s++) {
        float4 v = *(const float4*)(part + (size_t)s * partStride + e);
        acc.x += v.x; acc.y += v.y; acc.z += v.z; acc.w += v.w;
    }
    *(float4*)(out + e) = acc;
}

// ---------------- depthwise causal conv (D_CONV=4) + SiLU; writes u fp32 + split-bf16 ----------------
__global__ void __launch_bounds__(256)
conv_silu_kernel(const float* __restrict__ cw, const float* __restrict__ cb)
{
    int gid = blockIdx.x * 256 + threadIdx.x;   // over ROWS*DIN
    int d = gid & (DIN - 1);
    int row = gid >> 11;
    int t = row & (LL - 1);
    float acc = cb[d];
    const float* base = g_xz + (size_t)row * (2 * DIN) + d;
#pragma unroll
    for (int k = 0; k < DCONV; k++) {
        int off = k - (DCONV - 1);
        if (t + off >= 0)
            acc = fmaf(cw[d * DCONV + k], base[(long)off * (2 * DIN)], acc);
    }
    float s = acc * sigmoidf_(acc);
    g_u[gid] = s;
    split_store3(g_actb, (size_t)row * 6144, d, DIN, s);
}

// ---------------- selective scan v2: warp per (b,d) channel ----------------
#define GD 8
#define CT 32

__global__ void __launch_bounds__(256)
scan_kernel(const float* __restrict__ A_log, const float* __restrict__ Dw)
{
    __shared__ float sB[CT][DSTATE];
    __shared__ float sC[CT][DSTATE];
    __shared__ float sdt[CT][GD];
    __shared__ float su [CT][GD];
    __shared__ float sz [CT][GD];
    __shared__ float sp [GD][CT][33];

    const int tid = threadIdx.x;
    const int w = tid >> 5, lane = tid & 31;
    const int b = blockIdx.y;
    const int d0 = blockIdx.x * GD;
    const int d = d0 + w;

    const float L2E = 1.44269504f;
    const float a0 = -__expf(A_log[d * DSTATE + 2 * lane])     * L2E;
    const float a1 = -__expf(A_log[d * DSTATE + 2 * lane + 1]) * L2E;
    const float Dd = Dw[d];
    float h0 = 0.f, h1 = 0.f;

    const float* xdbl_b = g_xdbl + (size_t)b * LL * XDBL;
    const float* dt_b = g_dt + (size_t)b * LL * DIN + d0;
    const float* u_b  = g_u  + (size_t)b * LL * DIN + d0;
    const float* z_b  = g_xz + (size_t)b * LL * (2 * DIN) + DIN + d0;

    for (int t0 = 0; t0 < LL; t0 += CT) {
        __syncthreads();
#pragma unroll
        for (int r = 0; r < (CT * DSTATE) / 256; r++) {
            int e = tid + r * 256;
            int tt = e >> 6, n = e & 63;
            const float* src = xdbl_b + (size_t)(t0 + tt) * XDBL + DTRANK;
            sB[tt][n] = src[n];
            sC[tt][n] = src[DSTATE + n];
        }
        {
            int tt = tid >> 3, dd = tid & 7;
            sdt[tt][dd] = dt_b[(size_t)(t0 + tt) * DIN + dd];
            su [tt][dd] = u_b [(size_t)(t0 + tt) * DIN + dd];
            sz [tt][dd] = z_b [(size_t)(t0 + tt) * (2 * DIN) + dd];
        }
        __syncthreads();
#pragma unroll 8
        for (int tt = 0; tt < CT; tt++) {
            float dtv = sdt[tt][w], uv = su[tt][w];
            float2 Bv = *(const float2*)&sB[tt][2 * lane];
            float2 Cv = *(const float2*)&sC[tt][2 * lane];
            float dA0 = ex2_(dtv * a0);
            float dA1 = ex2_(dtv * a1);
            float du = dtv * uv;
            h0 = fmaf(dA0, h0, du * Bv.x);
            h1 = fmaf(dA1, h1, du * Bv.y);
            sp[w][tt][lane] = fmaf(h1, Cv.y, h0 * Cv.x);
        }
        __syncwarp();
        {
            const float* pr = &sp[w][lane][0];
            float sum = 0.f;
#pragma unroll
            for (int i = 0; i < 32; i++) sum += pr[i];
            float uvv = su[lane][w];
            float zvv = sz[lane][w];
            float yv = fmaf(uvv, Dd, sum);
            float o = yv * (zvv * sigmoidf_(zvv));
            split_store3(g_actb, (size_t)(b * LL + t0 + lane) * 6144, d, DIN, o);
        }
    }
}

// ---------------- launch ----------------
static inline int cdiv(int a, int b) { return (a + b - 1) / b; }

extern "C" void kernel_launch(void* const* d_in, const int* in_sizes, int n_in,
                              void* d_out, int out_size)
{
    const float* x         = (const float*)d_in[0];
    const float* ln1_g     = (const float*)d_in[1];
    const float* ln1_b     = (const float*)d_in[2];
    const float* in_proj_w = (const float*)d_in[3];
    const float* conv_w    = (const float*)d_in[4];
    const float* conv_b    = (const float*)d_in[5];
    const float* x_proj_w  = (const float*)d_in[6];
    const float* dt_w      = (const float*)d_in[7];
    const float* dt_b      = (const float*)d_in[8];
    const float* A_log     = (const float*)d_in[9];
    const float* D         = (const float*)d_in[10];
    const float* out_proj_w= (const float*)d_in[11];
    const float* ln2_g     = (const float*)d_in[12];
    const float* ln2_b     = (const float*)d_in[13];
    const float* w1        = (const float*)d_in[14];
    const float* b1        = (const float*)d_in[15];
    const float* w2        = (const float*)d_in[16];
    const float* b2        = (const float*)d_in[17];
    float* out = (float*)d_out;

    float *xz, *u, *xdbl, *dt, *x2, *part;
    __nv_bfloat16 *actb, *actb2, *wb;
    cudaGetSymbolAddress((void**)&xz,   g_xz);
    cudaGetSymbolAddress((void**)&u,    g_u);
    cudaGetSymbolAddress((void**)&xdbl, g_xdbl);
    cudaGetSymbolAddress((void**)&dt,   g_dt);
    cudaGetSymbolAddress((void**)&x2,   g_x2);
    cudaGetSymbolAddress((void**)&part, g_part);
    cudaGetSymbolAddress((void**)&actb, g_actb);
    cudaGetSymbolAddress((void**)&actb2,g_actb2);
    cudaGetSymbolAddress((void**)&wb,   g_wb);

    cudaFuncSetAttribute(hmma_gemm<0>, cudaFuncAttributeMaxDynamicSharedMemorySize, SMEMSZ);
    cudaFuncSetAttribute(hmma_gemm<1>, cudaFuncAttributeMaxDynamicSharedMemorySize, SMEMSZ);
    cudaFuncSetAttribute(hmma_gemm<2>, cudaFuncAttributeMaxDynamicSharedMemorySize, SMEMSZ);
    cudaFuncSetAttribute(hmma_gemm<4>, cudaFuncAttributeMaxDynamicSharedMemorySize, SMEMSZ);
    cudaFuncSetAttribute(hmma_gemm<5>, cudaFuncAttributeMaxDynamicSharedMemorySize, SMEMSZ);

    // 1. LN1 -> actb (split-bf16, K3p=1536)
    ln_kernel<<<ROWS, 128>>>(x, ln1_g, ln1_b, actb, 1e-5f);

    // 2. in_proj: xz = y @ in_proj_w^T  [2048 x 4096], K3=1536
    cvt_split<<<cdiv(4096 * DIM, 256), 256>>>(in_proj_w, DIM, DIM, 1536, 4096, wb, 1);
    hmma_gemm<0><<<dim3(64, 16, 1), 256, SMEMSZ>>>(actb, wb, xz, 2 * DIN, 1536, 1536, 0, nullptr, nullptr);

    // 3. causal conv + silu -> u (fp32) + actb (split-bf16, K3p=6144)
    conv_silu_kernel<<<(ROWS * DIN) / 256, 256>>>(conv_w, conv_b);

    // 4. x_proj: xdbl = u @ x_proj_w^T  [2048 x 160], K3=6144, split-K=4
    cvt_split<<<cdiv(XDBL * DIN, 256), 256>>>(x_proj_w, DIN, DIN, 6144, XDBL, wb, 1);
    hmma_gemm<0><<<dim3(3, 16, 4), 256, SMEMSZ>>>(actb, wb, part, XDBL, 6144, 1536,
                                                  (size_t)ROWS * XDBL, nullptr, nullptr);
    reduce_kernel<<<(ROWS * XDBL / 4 + 255) / 256, 256>>>(part, xdbl, ROWS * XDBL / 4, 4,
                                                          (size_t)ROWS * XDBL);

    // 5. dt = softplus(xdbl[:, :32] @ dt_w^T + dt_b)  [2048 x 2048], K3=96 pad 128
    cvt_split<<<cdiv(ROWS * DTRANK, 256), 256>>>(xdbl, XDBL, DTRANK, 128, ROWS, actb2, 0);
    cvt_split<<<cdiv(DIN * DTRANK, 256), 256>>>(dt_w, DTRANK, DTRANK, 128, DIN, wb, 1);
    pad_zero<<<cdiv(ROWS * 32, 256), 256>>>(actb2, 128, 96, ROWS);
    pad_zero<<<cdiv(DIN * 32, 256), 256>>>(wb, 128, 96, DIN);
    hmma_gemm<1><<<dim3(32, 16, 1), 256, SMEMSZ>>>(actb2, wb, dt, DIN, 128, 128, 0, dt_b, nullptr);

    // 6. selective scan -> actb (split-bf16, K3p=6144)
    scan_kernel<<<dim3(DIN / GD, BB), 256>>>(A_log, D);

    // 7. out_proj (fused resid): x2 = x + ys @ out_proj_w^T  [2048 x 512], K3=6144
    cvt_split<<<cdiv(DIM * DIN, 256), 256>>>(out_proj_w, DIN, DIN, 6144, DIM, wb, 1);
    hmma_gemm<2><<<dim3(8, 16, 1), 256, SMEMSZ>>>(actb, wb, x2, DIM, 6144, 6144, 0, nullptr, x);

    // 8. LN2 -> actb (split-bf16, K3p=1536)
    ln_kernel<<<ROWS, 128>>>(x2, ln2_g, ln2_b, actb, 1e-6f);

    // 9. h1 = gelu(y2 @ w1^T + b1) -> actb2 (split-bf16, K3p=6144)  [2048 x 2048], K3=1536
    cvt_split<<<cdiv(4 * DIM * DIM, 256), 256>>>(w1, DIM, DIM, 1536, 4 * DIM, wb, 1);
    hmma_gemm<5><<<dim3(32, 16, 1), 256, SMEMSZ>>>(actb, wb, nullptr, 4 * DIM, 1536, 1536, 0, b1, nullptr);

    // 10. out (fused bias+resid): out = x2 + h1 @ w2^T + b2  [2048 x 512], K3=6144
    cvt_split<<<cdiv(DIM * DIN, 256), 256>>>(w2, DIN, DIN, 6144, DIM, wb, 1);
    hmma_gemm<4><<<dim3(8, 16, 1), 256, SMEMSZ>>>(actb2, wb, out, DIM, 6144, 6144, 0, b2, x2);
}

// round 9
// speedup vs baseline: 1.0663x; 1.0624x over previous
#include <cuda_runtime.h>
#include <cuda_bf16.h>
#include <math.h>
#include <stdint.h>

#define BB 2
#define LL 1024
#define DIM 512
#define DSTATE 64
#define DCONV 4
#define DIN 2048
#define DTRANK 32
#define XDBL 160            // DT_RANK + 2*D_STATE
#define ROWS 2048           // B*L

// ---------------- scratch (device globals; no allocs allowed) ----------------
static __device__ __align__(16) float g_xz  [ROWS * 2 * DIN];
static __device__ __align__(16) float g_u   [ROWS * DIN];
static __device__ __align__(16) float g_xdbl[ROWS * XDBL];
static __device__ __align__(16) float g_dt  [ROWS * DIN];
static __device__ __align__(16) float g_x2  [ROWS * DIM];
static __device__ __align__(16) float g_part[4 * ROWS * DIM];                    // split-K partials
static __device__ __align__(16) __nv_bfloat16 g_actb [ROWS * 6144];              // A' split-bf16
static __device__ __align__(16) __nv_bfloat16 g_actb2[ROWS * 6144];              // A' (2nd, for MLP)
static __device__ __align__(16) __nv_bfloat16 g_wb  [4096 * 1536 + 512 * 6144]; // W' split-bf16

// ---------------- math helpers ----------------
__device__ __forceinline__ float sigmoidf_(float x) { return __fdividef(1.f, 1.f + __expf(-x)); }
__device__ __forceinline__ float softplusf_(float x){ return x > 20.f ? x : log1pf(__expf(x)); }
__device__ __forceinline__ float geluf_(float x)    { return 0.5f * x * (1.f + erff(x * 0.70710678118654752f)); }
__device__ __forceinline__ float ex2_(float x) {
    float r; asm("ex2.approx.f32 %0, %1;" : "=f"(r) : "f"(x)); return r;
}

__device__ __forceinline__ void split_store3(__nv_bfloat16* base, size_t rb, int k, int K, float v) {
    __nv_bfloat16 hi = __float2bfloat16(v);
    __nv_bfloat16 lo = __float2bfloat16(v - __bfloat162float(hi));
    base[rb + k] = hi; base[rb + K + k] = lo; base[rb + 2 * K + k] = hi;
}

// ---------------- PTX helpers (baseline ISA only: sm_80+, valid on sm_103) ----------------
__device__ __forceinline__ uint32_t smem_u32(const void* p) {
    uint32_t a;
    asm("{ .reg .u64 t; cvta.to.shared.u64 t, %1; cvt.u32.u64 %0, t; }" : "=r"(a) : "l"(p));
    return a;
}
__device__ __forceinline__ void cp16(uint32_t dst, const void* src, int srcsize) {
    asm volatile("cp.async.cg.shared.global [%0], [%1], 16, %2;" :: "r"(dst), "l"(src), "r"(srcsize) : "memory");
}
#define CP_COMMIT() asm volatile("cp.async.commit_group;" ::: "memory")
#define CP_WAIT2()  asm volatile("cp.async.wait_group 2;" ::: "memory")
#define CP_WAIT1()  asm volatile("cp.async.wait_group 1;" ::: "memory")

__device__ __forceinline__ void ldsm4(uint32_t& r0, uint32_t& r1, uint32_t& r2, uint32_t& r3, uint32_t addr) {
    asm volatile("ldmatrix.sync.aligned.m8n8.x4.shared.b16 {%0,%1,%2,%3}, [%4];"
                 : "=r"(r0), "=r"(r1), "=r"(r2), "=r"(r3) : "r"(addr));
}
__device__ __forceinline__ void mma16816(float* c, const uint32_t* a, const uint32_t* b) {
    asm volatile("mma.sync.aligned.m16n8k16.row.col.f32.bf16.bf16.f32 "
                 "{%0,%1,%2,%3}, {%4,%5,%6,%7}, {%8,%9}, {%0,%1,%2,%3};"
                 : "+f"(c[0]), "+f"(c[1]), "+f"(c[2]), "+f"(c[3])
                 : "r"(a[0]), "r"(a[1]), "r"(a[2]), "r"(a[3]), "r"(b[0]), "r"(b[1]));
}

// ---------------- LayerNorm (writes split-bf16 3-plane directly, K=512 -> K3p=1536) ----------------
__global__ void __launch_bounds__(128)
ln_kernel(const float* __restrict__ x, const float* __restrict__ g,
          const float* __restrict__ b, __nv_bfloat16* __restrict__ outb, float eps)
{
    int row = blockIdx.x;
    const float* xr = x + (size_t)row * DIM;
    float v[4];
    float s = 0.f;
#pragma unroll
    for (int i = 0; i < 4; i++) { v[i] = xr[threadIdx.x + i * 128]; s += v[i]; }
    __shared__ float red[8];
#pragma unroll
    for (int o = 16; o > 0; o >>= 1) s += __shfl_xor_sync(0xffffffffu, s, o);
    if ((threadIdx.x & 31) == 0) red[threadIdx.x >> 5] = s;
    __syncthreads();
    float mean = (red[0] + red[1] + red[2] + red[3]) * (1.f / DIM);
    float s2 = 0.f;
#pragma unroll
    for (int i = 0; i < 4; i++) { float d = v[i] - mean; s2 += d * d; }
#pragma unroll
    for (int o = 16; o > 0; o >>= 1) s2 += __shfl_xor_sync(0xffffffffu, s2, o);
    if ((threadIdx.x & 31) == 0) red[4 + (threadIdx.x >> 5)] = s2;
    __syncthreads();
    float var = (red[4] + red[5] + red[6] + red[7]) * (1.f / DIM);
    float rstd = rsqrtf(var + eps);
    size_t rb = (size_t)row * 1536;
#pragma unroll
    for (int i = 0; i < 4; i++) {
        int c = threadIdx.x + i * 128;
        float o = (v[i] - mean) * rstd * g[c] + b[c];
        split_store3(outb, rb, c, DIM, o);
    }
}

// ---------------- fp32 -> split-bf16 (3-plane) conversion ----------------
__global__ void __launch_bounds__(256)
cvt_split(const float* __restrict__ src, int lda, int K, int K3p, int rows,
          __nv_bfloat16* __restrict__ dst, int mode)
{
    int i = blockIdx.x * 256 + threadIdx.x;
    if (i >= rows * K) return;
    int r = i / K, k = i - r * K;
    float a = src[(size_t)r * lda + k];
    __nv_bfloat16 hi = __float2bfloat16(a);
    __nv_bfloat16 lo = __float2bfloat16(a - __bfloat162float(hi));
    __nv_bfloat16* dr = dst + (size_t)r * K3p;
    if (mode == 0) { dr[k] = hi; dr[K + k] = lo;  dr[2 * K + k] = hi; }
    else           { dr[k] = hi; dr[K + k] = hi;  dr[2 * K + k] = lo; }
}

__global__ void __launch_bounds__(256)
pad_zero(__nv_bfloat16* __restrict__ dst, int K3p, int k0, int rows)
{
    int pad = K3p - k0;
    int i = blockIdx.x * 256 + threadIdx.x;
    if (i >= rows * pad) return;
    int r = i / pad, k = i - r * pad;
    dst[(size_t)r * K3p + k0 + k] = __float2bfloat16(0.f);
}

#define APITCH 80                       // 32 bf16 (64B) + 16B pad

// ---------------- HMMA GEMM (narrow): BM=128, BN=64, 256 thr, warp tile 32x32 ----------------
// 4-stage cp.async pipeline, 1 barrier/chunk. EPI: 0 none, 2 +resid, 4 bias+resid
#define STAGE_BYTES (128 * APITCH + 64 * APITCH)   // 15360
#define SMEMSZ (4 * STAGE_BYTES)                    // 61440
template<int EPI>
__global__ void __launch_bounds__(256)
hmma_gemm(const __nv_bfloat16* __restrict__ A, const __nv_bfloat16* __restrict__ W,
          float* __restrict__ C, int N, int K3, int Ksl, size_t partStride,
          const float* __restrict__ bias, const float* __restrict__ resid)
{
    extern __shared__ __align__(16) char dsm[];

    const int tid = threadIdx.x;
    const int lane = tid & 31, wid = tid >> 5;
    const int warpM = (wid & 3) * 32;     // 4 warps along M
    const int warpN = (wid >> 2) * 32;    // 2 warps along N
    const int m0 = blockIdx.y * 128;
    const int n0 = blockIdx.x * 64;
    const int koff = blockIdx.z * Ksl;
    const int NC = Ksl / 32;
    C += (size_t)blockIdx.z * partStride;

    const uint32_t sbase = smem_u32(dsm);
    uint32_t aB[4], bB[4];
#pragma unroll
    for (int s = 0; s < 4; s++) { aB[s] = sbase + s * STAGE_BYTES; bB[s] = aB[s] + 128 * APITCH; }

    const int lr = tid >> 2, lseg = tid & 3;
    const uint32_t aLdOff = (uint32_t)((warpM + (lane & 15)) * APITCH + (lane >> 4) * 16);
    const uint32_t bLdOff = (uint32_t)((warpN + (lane & 7)) * APITCH + (lane >> 3) * 16);

    float acc[2][4][4];
#pragma unroll
    for (int i = 0; i < 2; i++)
#pragma unroll
        for (int j = 0; j < 4; j++)
#pragma unroll
            for (int q = 0; q < 4; q++) acc[i][j][q] = 0.f;

    auto load_chunk = [&](int buf, int c) {
        const __nv_bfloat16* asrc = A + (size_t)(m0 + lr) * K3 + koff + c * 32 + lseg * 8;
        cp16(aB[buf] + (uint32_t)(lr * APITCH + lseg * 16), asrc, 16);
        const __nv_bfloat16* asrc2 = asrc + (size_t)64 * K3;
        cp16(aB[buf] + (uint32_t)((lr + 64) * APITCH + lseg * 16), asrc2, 16);
        if (lr < 64) {
            int brow = n0 + lr;
            bool bv = (brow < N);
            const __nv_bfloat16* bsrc = W + (size_t)(bv ? brow : 0) * K3 + koff + c * 32 + lseg * 8;
            cp16(bB[buf] + (uint32_t)(lr * APITCH + lseg * 16), bsrc, bv ? 16 : 0);
        }
    };

    const int pf = NC < 3 ? NC : 3;
    for (int p = 0; p < pf; p++) { load_chunk(p, p); CP_COMMIT(); }

    for (int c = 0; c < NC; c++) {
        CP_WAIT2();
        __syncthreads();
        if (c + 3 < NC) { load_chunk((c + 3) & 3, c + 3); CP_COMMIT(); }
        const int buf = c & 3;

        uint32_t aF[2][2][4];
#pragma unroll
        for (int mt = 0; mt < 2; mt++)
#pragma unroll
            for (int kh = 0; kh < 2; kh++)
                ldsm4(aF[mt][kh][0], aF[mt][kh][1], aF[mt][kh][2], aF[mt][kh][3],
                      aB[buf] + aLdOff + (uint32_t)(mt * 16 * APITCH + kh * 32));
        uint32_t bF[4][4];
#pragma unroll
        for (int nt = 0; nt < 4; nt++)
            ldsm4(bF[nt][0], bF[nt][1], bF[nt][2], bF[nt][3],
                  bB[buf] + bLdOff + (uint32_t)(nt * 8 * APITCH));
#pragma unroll
        for (int kh = 0; kh < 2; kh++)
#pragma unroll
            for (int mt = 0; mt < 2; mt++)
#pragma unroll
                for (int nt = 0; nt < 4; nt++)
                    mma16816(acc[mt][nt], aF[mt][kh], &bF[nt][kh * 2]);
    }

    // ---- epilogue ----
#pragma unroll
    for (int mt = 0; mt < 2; mt++) {
        int row = m0 + warpM + mt * 16 + (lane >> 2);
#pragma unroll
        for (int nt = 0; nt < 4; nt++) {
            int col = n0 + warpN + nt * 8 + 2 * (lane & 3);
            if (col < N) {
                float v0 = acc[mt][nt][0], v1 = acc[mt][nt][1];
                float v2 = acc[mt][nt][2], v3 = acc[mt][nt][3];
                if (EPI == 4) {
                    float b0 = bias[col], b1 = bias[col + 1];
                    v0 += b0; v1 += b1; v2 += b0; v3 += b1;
                }
                size_t i0 = (size_t)row * N + col;
                size_t i1 = (size_t)(row + 8) * N + col;
                if (EPI == 2 || EPI == 4) {
                    float2 r0 = *(const float2*)&resid[i0];
                    float2 r1 = *(const float2*)&resid[i1];
                    v0 += r0.x; v1 += r0.y; v2 += r1.x; v3 += r1.y;
                }
                *(float2*)&C[i0] = make_float2(v0, v1);
                *(float2*)&C[i1] = make_float2(v2, v3);
            }
        }
    }
}

// ---------------- HMMA GEMM (wide): BM=64, BN=128, 128 thr, warp tile 32x64 ----------------
// Requires N % 128 == 0 and M % 64 == 0 (in_proj, dt, w1). 3-stage pipeline.
// EPI: 0 none, 1 bias+softplus, 5 bias+gelu -> split-bf16 into g_actb2 (K=2048,K3p=6144)
#define STAGEW_BYTES (64 * APITCH + 128 * APITCH)  // 15360
#define SMEMSZW (3 * STAGEW_BYTES)                  // 46080
template<int EPI>
__global__ void __launch_bounds__(128)
hmma_gemmW(const __nv_bfloat16* __restrict__ A, const __nv_bfloat16* __restrict__ W,
           float* __restrict__ C, int N, int K3,
           const float* __restrict__ bias)
{
    extern __shared__ __align__(16) char dsm[];

    const int tid = threadIdx.x;
    const int lane = tid & 31, wid = tid >> 5;
    const int warpM = (wid & 1) * 32;     // 2 warps along M
    const int warpN = (wid >> 1) * 64;    // 2 warps along N
    const int m0 = blockIdx.y * 64;
    const int n0 = blockIdx.x * 128;
    const int NC = K3 / 32;

    const uint32_t sbase = smem_u32(dsm);
    uint32_t aB[3], bB[3];
#pragma unroll
    for (int s = 0; s < 3; s++) { aB[s] = sbase + s * STAGEW_BYTES; bB[s] = aB[s] + 64 * APITCH; }

    const int lr = tid >> 2, lseg = tid & 3;   // lr 0..31
    const uint32_t aLdOff = (uint32_t)((warpM + (lane & 15)) * APITCH + (lane >> 4) * 16);
    const uint32_t bLdOff = (uint32_t)((warpN + (lane & 7)) * APITCH + (lane >> 3) * 16);

    float acc[2][8][4];
#pragma unroll
    for (int i = 0; i < 2; i++)
#pragma unroll
        for (int j = 0; j < 8; j++)
#pragma unroll
            for (int q = 0; q < 4; q++) acc[i][j][q] = 0.f;

    auto load_chunk = [&](int buf, int c) {
        const __nv_bfloat16* asrc = A + (size_t)(m0 + lr) * K3 + c * 32 + lseg * 8;
        cp16(aB[buf] + (uint32_t)(lr * APITCH + lseg * 16), asrc, 16);
        cp16(aB[buf] + (uint32_t)((lr + 32) * APITCH + lseg * 16), asrc + (size_t)32 * K3, 16);
        const __nv_bfloat16* bsrc = W + (size_t)(n0 + lr) * K3 + c * 32 + lseg * 8;
        cp16(bB[buf] + (uint32_t)(lr * APITCH + lseg * 16), bsrc, 16);
        cp16(bB[buf] + (uint32_t)((lr + 32) * APITCH + lseg * 16), bsrc + (size_t)32 * K3, 16);
        cp16(bB[buf] + (uint32_t)((lr + 64) * APITCH + lseg * 16), bsrc + (size_t)64 * K3, 16);
        cp16(bB[buf] + (uint32_t)((lr + 96) * APITCH + lseg * 16), bsrc + (size_t)96 * K3, 16);
    };

    const int pf = NC < 2 ? NC : 2;
    for (int p = 0; p < pf; p++) { load_chunk(p, p); CP_COMMIT(); }

    for (int c = 0; c < NC; c++) {
        CP_WAIT1();
        __syncthreads();
        if (c + 2 < NC) { load_chunk((c + 2) % 3, c + 2); CP_COMMIT(); }
        const int buf = c % 3;

        uint32_t aF[2][2][4];
#pragma unroll
        for (int mt = 0; mt < 2; mt++)
#pragma unroll
            for (int kh = 0; kh < 2; kh++)
                ldsm4(aF[mt][kh][0], aF[mt][kh][1], aF[mt][kh][2], aF[mt][kh][3],
                      aB[buf] + aLdOff + (uint32_t)(mt * 16 * APITCH + kh * 32));
#pragma unroll
        for (int half = 0; half < 2; half++) {
            uint32_t bF[4][4];
#pragma unroll
            for (int j = 0; j < 4; j++)
                ldsm4(bF[j][0], bF[j][1], bF[j][2], bF[j][3],
                      bB[buf] + bLdOff + (uint32_t)((half * 4 + j) * 8 * APITCH));
#pragma unroll
            for (int kh = 0; kh < 2; kh++)
#pragma unroll
                for (int mt = 0; mt < 2; mt++)
#pragma unroll
                    for (int j = 0; j < 4; j++)
                        mma16816(acc[mt][half * 4 + j], aF[mt][kh], &bF[j][kh * 2]);
        }
    }

    // ---- epilogue ----
#pragma unroll
    for (int mt = 0; mt < 2; mt++) {
        int row = m0 + warpM + mt * 16 + (lane >> 2);
#pragma unroll
        for (int nt = 0; nt < 8; nt++) {
            int col = n0 + warpN + nt * 8 + 2 * (lane & 3);
            float v0 = acc[mt][nt][0], v1 = acc[mt][nt][1];
            float v2 = acc[mt][nt][2], v3 = acc[mt][nt][3];
            if (EPI == 1) {
                float b0 = bias[col], b1 = bias[col + 1];
                v0 = softplusf_(v0 + b0); v1 = softplusf_(v1 + b1);
                v2 = softplusf_(v2 + b0); v3 = softplusf_(v3 + b1);
            } else if (EPI == 5) {
                float b0 = bias[col], b1 = bias[col + 1];
                v0 = geluf_(v0 + b0); v1 = geluf_(v1 + b1);
                v2 = geluf_(v2 + b0); v3 = geluf_(v3 + b1);
            }
            if (EPI == 5) {
                size_t rb0 = (size_t)row * 6144;
                size_t rb1 = (size_t)(row + 8) * 6144;
                split_store3(g_actb2, rb0, col,     2048, v0);
                split_store3(g_actb2, rb0, col + 1, 2048, v1);
                split_store3(g_actb2, rb1, col,     2048, v2);
                split_store3(g_actb2, rb1, col + 1, 2048, v3);
            } else {
                *(float2*)&C[(size_t)row * N + col]       = make_float2(v0, v1);
                *(float2*)&C[(size_t)(row + 8) * N + col] = make_float2(v2, v3);
            }
        }
    }
}

// ---------------- split-K reduce (+epilogue). REPI: 0 sum, 2 sum+resid, 4 sum+bias+resid
template<int REPI>
__global__ void __launch_bounds__(256)
reduce_kernel(const float* __restrict__ part, float* __restrict__ out,
              int total4, int slices, size_t partStride, int ldc,
              const float* __restrict__ bias, const float* __restrict__ resid)
{
    int i = blockIdx.x * 256 + threadIdx.x;
    if (i >= total4) return;
    size_t e = (size_t)i * 4;
    float4 acc = *(const float4*)(part + e);
    for (int s = 1; s < slices; s++) {
        float4 v = *(const float4*)(part + (size_t)s * partStride + e);
        acc.x += v.x; acc.y += v.y; acc.z += v.z; acc.w += v.w;
    }
    if (REPI >= 4) {
        int n = (int)(e % ldc);
        acc.x += bias[n]; acc.y += bias[n + 1]; acc.z += bias[n + 2]; acc.w += bias[n + 3];
    }
    if (REPI >= 2) {
        float4 r = *(const float4*)(resid + e);
        acc.x += r.x; acc.y += r.y; acc.z += r.z; acc.w += r.w;
    }
    *(float4*)(out + e) = acc;
}

// ---------------- depthwise causal conv (D_CONV=4) + SiLU; writes u fp32 + split-bf16 ----------------
__global__ void __launch_bounds__(256)
conv_silu_kernel(const float* __restrict__ cw, const float* __restrict__ cb)
{
    int gid = blockIdx.x * 256 + threadIdx.x;   // over ROWS*DIN
    int d = gid & (DIN - 1);
    int row = gid >> 11;
    int t = row & (LL - 1);
    float acc = cb[d];
    const float* base = g_xz + (size_t)row * (2 * DIN) + d;
#pragma unroll
    for (int k = 0; k < DCONV; k++) {
        int off = k - (DCONV - 1);
        if (t + off >= 0)
            acc = fmaf(cw[d * DCONV + k], base[(long)off * (2 * DIN)], acc);
    }
    float s = acc * sigmoidf_(acc);
    g_u[gid] = s;
    split_store3(g_actb, (size_t)row * 6144, d, DIN, s);
}

// ---------------- selective scan v2: warp per (b,d) channel ----------------
#define GD 8
#define CT 32

__global__ void __launch_bounds__(256)
scan_kernel(const float* __restrict__ A_log, const float* __restrict__ Dw)
{
    __shared__ float sB[CT][DSTATE];
    __shared__ float sC[CT][DSTATE];
    __shared__ float sdt[CT][GD];
    __shared__ float su [CT][GD];
    __shared__ float sz [CT][GD];
    __shared__ float sp [GD][CT][33];

    const int tid = threadIdx.x;
    const int w = tid >> 5, lane = tid & 31;
    const int b = blockIdx.y;
    const int d0 = blockIdx.x * GD;
    const int d = d0 + w;

    const float L2E = 1.44269504f;
    const float a0 = -__expf(A_log[d * DSTATE + 2 * lane])     * L2E;
    const float a1 = -__expf(A_log[d * DSTATE + 2 * lane + 1]) * L2E;
    const float Dd = Dw[d];
    float h0 = 0.f, h1 = 0.f;

    const float* xdbl_b = g_xdbl + (size_t)b * LL * XDBL;
    const float* dt_b = g_dt + (size_t)b * LL * DIN + d0;
    const float* u_b  = g_u  + (size_t)b * LL * DIN + d0;
    const float* z_b  = g_xz + (size_t)b * LL * (2 * DIN) + DIN + d0;

    for (int t0 = 0; t0 < LL; t0 += CT) {
        __syncthreads();
#pragma unroll
        for (int r = 0; r < (CT * DSTATE) / 256; r++) {
            int e = tid + r * 256;
            int tt = e >> 6, n = e & 63;
            const float* src = xdbl_b + (size_t)(t0 + tt) * XDBL + DTRANK;
            sB[tt][n] = src[n];
            sC[tt][n] = src[DSTATE + n];
        }
        {
            int tt = tid >> 3, dd = tid & 7;
            sdt[tt][dd] = dt_b[(size_t)(t0 + tt) * DIN + dd];
            su [tt][dd] = u_b [(size_t)(t0 + tt) * DIN + dd];
            sz [tt][dd] = z_b [(size_t)(t0 + tt) * (2 * DIN) + dd];
        }
        __syncthreads();
#pragma unroll 8
        for (int tt = 0; tt < CT; tt++) {
            float dtv = sdt[tt][w], uv = su[tt][w];
            float2 Bv = *(const float2*)&sB[tt][2 * lane];
            float2 Cv = *(const float2*)&sC[tt][2 * lane];
            float dA0 = ex2_(dtv * a0);
            float dA1 = ex2_(dtv * a1);
            float du = dtv * uv;
            h0 = fmaf(dA0, h0, du * Bv.x);
            h1 = fmaf(dA1, h1, du * Bv.y);
            sp[w][tt][lane] = fmaf(h1, Cv.y, h0 * Cv.x);
        }
        __syncwarp();
        {
            const float* pr = &sp[w][lane][0];
            float sum = 0.f;
#pragma unroll
            for (int i = 0; i < 32; i++) sum += pr[i];
            float uvv = su[lane][w];
            float zvv = sz[lane][w];
            float yv = fmaf(uvv, Dd, sum);
            float o = yv * (zvv * sigmoidf_(zvv));
            split_store3(g_actb, (size_t)(b * LL + t0 + lane) * 6144, d, DIN, o);
        }
    }
}

// ---------------- launch ----------------
static inline int cdiv(int a, int b) { return (a + b - 1) / b; }

extern "C" void kernel_launch(void* const* d_in, const int* in_sizes, int n_in,
                              void* d_out, int out_size)
{
    const float* x         = (const float*)d_in[0];
    const float* ln1_g     = (const float*)d_in[1];
    const float* ln1_b     = (const float*)d_in[2];
    const float* in_proj_w = (const float*)d_in[3];
    const float* conv_w    = (const float*)d_in[4];
    const float* conv_b    = (const float*)d_in[5];
    const float* x_proj_w  = (const float*)d_in[6];
    const float* dt_w      = (const float*)d_in[7];
    const float* dt_b      = (const float*)d_in[8];
    const float* A_log     = (const float*)d_in[9];
    const float* D         = (const float*)d_in[10];
    const float* out_proj_w= (const float*)d_in[11];
    const float* ln2_g     = (const float*)d_in[12];
    const float* ln2_b     = (const float*)d_in[13];
    const float* w1        = (const float*)d_in[14];
    const float* b1        = (const float*)d_in[15];
    const float* w2        = (const float*)d_in[16];
    const float* b2        = (const float*)d_in[17];
    float* out = (float*)d_out;

    float *xz, *u, *xdbl, *dt, *x2, *part;
    __nv_bfloat16 *actb, *actb2, *wb;
    cudaGetSymbolAddress((void**)&xz,   g_xz);
    cudaGetSymbolAddress((void**)&u,    g_u);
    cudaGetSymbolAddress((void**)&xdbl, g_xdbl);
    cudaGetSymbolAddress((void**)&dt,   g_dt);
    cudaGetSymbolAddress((void**)&x2,   g_x2);
    cudaGetSymbolAddress((void**)&part, g_part);
    cudaGetSymbolAddress((void**)&actb, g_actb);
    cudaGetSymbolAddress((void**)&actb2,g_actb2);
    cudaGetSymbolAddress((void**)&wb,   g_wb);

    cudaFuncSetAttribute(hmma_gemm<0>,  cudaFuncAttributeMaxDynamicSharedMemorySize, SMEMSZ);
    cudaFuncSetAttribute(hmma_gemm<2>,  cudaFuncAttributeMaxDynamicSharedMemorySize, SMEMSZ);
    cudaFuncSetAttribute(hmma_gemm<4>,  cudaFuncAttributeMaxDynamicSharedMemorySize, SMEMSZ);
    cudaFuncSetAttribute(hmma_gemmW<0>, cudaFuncAttributeMaxDynamicSharedMemorySize, SMEMSZW);
    cudaFuncSetAttribute(hmma_gemmW<1>, cudaFuncAttributeMaxDynamicSharedMemorySize, SMEMSZW);
    cudaFuncSetAttribute(hmma_gemmW<5>, cudaFuncAttributeMaxDynamicSharedMemorySize, SMEMSZW);

    // 1. LN1 -> actb (split-bf16, K3p=1536)
    ln_kernel<<<ROWS, 128>>>(x, ln1_g, ln1_b, actb, 1e-5f);

    // 2. in_proj: xz = y @ in_proj_w^T  [2048 x 4096], K3=1536  (wide kernel)
    cvt_split<<<cdiv(4096 * DIM, 256), 256>>>(in_proj_w, DIM, DIM, 1536, 4096, wb, 1);
    hmma_gemmW<0><<<dim3(32, 32), 128, SMEMSZW>>>(actb, wb, xz, 2 * DIN, 1536, nullptr);

    // 3. causal conv + silu -> u (fp32) + actb (split-bf16, K3p=6144)
    conv_silu_kernel<<<(ROWS * DIN) / 256, 256>>>(conv_w, conv_b);

    // 4. x_proj: xdbl = u @ x_proj_w^T  [2048 x 160], K3=6144, split-K=4 (narrow kernel)
    cvt_split<<<cdiv(XDBL * DIN, 256), 256>>>(x_proj_w, DIN, DIN, 6144, XDBL, wb, 1);
    hmma_gemm<0><<<dim3(3, 16, 4), 256, SMEMSZ>>>(actb, wb, part, XDBL, 6144, 1536,
                                                  (size_t)ROWS * XDBL, nullptr, nullptr);
    reduce_kernel<0><<<(ROWS * XDBL / 4 + 255) / 256, 256>>>(part, xdbl, ROWS * XDBL / 4, 4,
                                                             (size_t)ROWS * XDBL, XDBL, nullptr, nullptr);

    // 5. dt = softplus(xdbl[:, :32] @ dt_w^T + dt_b)  [2048 x 2048], K3=96 pad 128 (wide kernel)
    cvt_split<<<cdiv(ROWS * DTRANK, 256), 256>>>(xdbl, XDBL, DTRANK, 128, ROWS, actb2, 0);
    cvt_split<<<cdiv(DIN * DTRANK, 256), 256>>>(dt_w, DTRANK, DTRANK, 128, DIN, wb, 1);
    pad_zero<<<cdiv(ROWS * 32, 256), 256>>>(actb2, 128, 96, ROWS);
    pad_zero<<<cdiv(DIN * 32, 256), 256>>>(wb, 128, 96, DIN);
    hmma_gemmW<1><<<dim3(16, 32), 128, SMEMSZW>>>(actb2, wb, dt, DIN, 128, dt_b);

    // 6. selective scan -> actb (split-bf16, K3p=6144)
    scan_kernel<<<dim3(DIN / GD, BB), 256>>>(A_log, D);

    // 7. out_proj: x2 = x + ys @ out_proj_w^T  [2048 x 512], K3=6144, split-K=2 (narrow)
    cvt_split<<<cdiv(DIM * DIN, 256), 256>>>(out_proj_w, DIN, DIN, 6144, DIM, wb, 1);
    hmma_gemm<0><<<dim3(8, 16, 2), 256, SMEMSZ>>>(actb, wb, part, DIM, 6144, 3072,
                                                  (size_t)ROWS * DIM, nullptr, nullptr);
    reduce_kernel<2><<<(ROWS * DIM / 4 + 255) / 256, 256>>>(part, x2, ROWS * DIM / 4, 2,
                                                            (size_t)ROWS * DIM, DIM, nullptr, x);

    // 8. LN2 -> actb (split-bf16, K3p=1536)
    ln_kernel<<<ROWS, 128>>>(x2, ln2_g, ln2_b, actb, 1e-6f);

    // 9. h1 = gelu(y2 @ w1^T + b1) -> actb2 (split-bf16, K3p=6144)  [2048 x 2048], K3=1536 (wide)
    cvt_split<<<cdiv(4 * DIM * DIM, 256), 256>>>(w1, DIM, DIM, 1536, 4 * DIM, wb, 1);
    hmma_gemmW<5><<<dim3(16, 32), 128, SMEMSZW>>>(actb, wb, nullptr, 4 * DIM, 1536, b1);

    // 10. out = x2 + h1 @ w2^T + b2  [2048 x 512], K3=6144, split-K=2 (narrow)
    cvt_split<<<cdiv(DIM * DIN, 256), 256>>>(w2, DIN, DIN, 6144, DIM, wb, 1);
    hmma_gemm<0><<<dim3(8, 16, 2), 256, SMEMSZ>>>(actb2, wb, part, DIM, 6144, 3072,
                                                  (size_t)ROWS * DIM, nullptr, nullptr);
    reduce_kernel<4><<<(ROWS * DIM / 4 + 255) / 256, 256>>>(part, out, ROWS * DIM / 4, 2,
                                                            (size_t)ROWS * DIM, DIM, b2, x2);
}

// round 10
// speedup vs baseline: 1.1040x; 1.0354x over previous
#include <cuda_runtime.h>
#include <cuda_bf16.h>
#include <math.h>
#include <stdint.h>

#define BB 2
#define LL 1024
#define DIM 512
#define DSTATE 64
#define DCONV 4
#define DIN 2048
#define DTRANK 32
#define XDBL 160            // DT_RANK + 2*D_STATE
#define ROWS 2048           // B*L

// weight-plane regions inside g_wb (split-bf16, K3p layout)
#define OFF_IP 0                    // in_proj : 4096 x 1536
#define OFF_XP 6291456              // x_proj  : 160  x 6144
#define OFF_DT 7274496              // dt      : 2048 x 128
#define OFF_OP 7536640              // out_proj: 512  x 6144
#define OFF_W1 10682368             // w1      : 2048 x 1536
#define OFF_W2 13828096             // w2      : 512  x 6144
#define WB_TOTAL 16973824

// ---------------- scratch (device globals; no allocs allowed) ----------------
static __device__ __align__(16) float g_xz  [ROWS * 2 * DIN];
static __device__ __align__(16) float g_u   [ROWS * DIN];
static __device__ __align__(16) float g_xdbl[ROWS * XDBL];
static __device__ __align__(16) float g_dt  [ROWS * DIN];
static __device__ __align__(16) float g_x2  [ROWS * DIM];
static __device__ __align__(16) float g_part[8 * ROWS * DIM];                    // split-K partials
static __device__ __align__(16) __nv_bfloat16 g_actb [ROWS * 6144];              // A' split-bf16
static __device__ __align__(16) __nv_bfloat16 g_actb2[ROWS * 6144];              // A' (2nd, for MLP)
static __device__ __align__(16) __nv_bfloat16 g_wb  [WB_TOTAL];                  // W' split-bf16 (all 6)

// ---------------- math helpers ----------------
__device__ __forceinline__ float sigmoidf_(float x) { return __fdividef(1.f, 1.f + __expf(-x)); }
__device__ __forceinline__ float softplusf_(float x){ return x > 20.f ? x : log1pf(__expf(x)); }
__device__ __forceinline__ float geluf_(float x)    { return 0.5f * x * (1.f + erff(x * 0.70710678118654752f)); }
__device__ __forceinline__ float ex2_(float x) {
    float r; asm("ex2.approx.f32 %0, %1;" : "=f"(r) : "f"(x)); return r;
}

__device__ __forceinline__ void split_store3(__nv_bfloat16* base, size_t rb, int k, int K, float v) {
    __nv_bfloat16 hi = __float2bfloat16(v);
    __nv_bfloat16 lo = __float2bfloat16(v - __bfloat162float(hi));
    base[rb + k] = hi; base[rb + K + k] = lo; base[rb + 2 * K + k] = hi;
}

// weight mode: [0,K)=hi [K,2K)=hi [2K,3K)=lo
__device__ __forceinline__ void wsplit(const float* __restrict__ src, int idx, int K, int K3p,
                                       __nv_bfloat16* __restrict__ dst) {
    int r = idx / K, k = idx - r * K;
    float a = src[(size_t)r * K + k];
    __nv_bfloat16 hi = __float2bfloat16(a);
    __nv_bfloat16 lo = __float2bfloat16(a - __bfloat162float(hi));
    __nv_bfloat16* dr = dst + (size_t)r * K3p;
    dr[k] = hi; dr[K + k] = hi; dr[2 * K + k] = lo;
}

// ---------------- PTX helpers (baseline ISA only: sm_80+, valid on sm_103) ----------------
__device__ __forceinline__ uint32_t smem_u32(const void* p) {
    uint32_t a;
    asm("{ .reg .u64 t; cvta.to.shared.u64 t, %1; cvt.u32.u64 %0, t; }" : "=r"(a) : "l"(p));
    return a;
}
__device__ __forceinline__ void cp16(uint32_t dst, const void* src, int srcsize) {
    asm volatile("cp.async.cg.shared.global [%0], [%1], 16, %2;" :: "r"(dst), "l"(src), "r"(srcsize) : "memory");
}
#define CP_COMMIT() asm volatile("cp.async.commit_group;" ::: "memory")
#define CP_WAIT2()  asm volatile("cp.async.wait_group 2;" ::: "memory")
#define CP_WAIT1()  asm volatile("cp.async.wait_group 1;" ::: "memory")

__device__ __forceinline__ void ldsm4(uint32_t& r0, uint32_t& r1, uint32_t& r2, uint32_t& r3, uint32_t addr) {
    asm volatile("ldmatrix.sync.aligned.m8n8.x4.shared.b16 {%0,%1,%2,%3}, [%4];"
                 : "=r"(r0), "=r"(r1), "=r"(r2), "=r"(r3) : "r"(addr));
}
__device__ __forceinline__ void mma16816(float* c, const uint32_t* a, const uint32_t* b) {
    asm volatile("mma.sync.aligned.m16n8k16.row.col.f32.bf16.bf16.f32 "
                 "{%0,%1,%2,%3}, {%4,%5,%6,%7}, {%8,%9}, {%0,%1,%2,%3};"
                 : "+f"(c[0]), "+f"(c[1]), "+f"(c[2]), "+f"(c[3])
                 : "r"(a[0]), "r"(a[1]), "r"(a[2]), "r"(a[3]), "r"(b[0]), "r"(b[1]));
}

// ---------------- LayerNorm (writes split-bf16 3-plane directly, K=512 -> K3p=1536) ----------------
__global__ void __launch_bounds__(128)
ln_kernel(const float* __restrict__ x, const float* __restrict__ g,
          const float* __restrict__ b, __nv_bfloat16* __restrict__ outb, float eps)
{
    int row = blockIdx.x;
    const float* xr = x + (size_t)row * DIM;
    float v[4];
    float s = 0.f;
#pragma unroll
    for (int i = 0; i < 4; i++) { v[i] = xr[threadIdx.x + i * 128]; s += v[i]; }
    __shared__ float red[8];
#pragma unroll
    for (int o = 16; o > 0; o >>= 1) s += __shfl_xor_sync(0xffffffffu, s, o);
    if ((threadIdx.x & 31) == 0) red[threadIdx.x >> 5] = s;
    __syncthreads();
    float mean = (red[0] + red[1] + red[2] + red[3]) * (1.f / DIM);
    float s2 = 0.f;
#pragma unroll
    for (int i = 0; i < 4; i++) { float d = v[i] - mean; s2 += d * d; }
#pragma unroll
    for (int o = 16; o > 0; o >>= 1) s2 += __shfl_xor_sync(0xffffffffu, s2, o);
    if ((threadIdx.x & 31) == 0) red[4 + (threadIdx.x >> 5)] = s2;
    __syncthreads();
    float var = (red[4] + red[5] + red[6] + red[7]) * (1.f / DIM);
    float rstd = rsqrtf(var + eps);
    size_t rb = (size_t)row * 1536;
#pragma unroll
    for (int i = 0; i < 4; i++) {
        int c = threadIdx.x + i * 128;
        float o = (v[i] - mean) * rstd * g[c] + b[c];
        split_store3(outb, rb, c, DIM, o);
    }
}

// ---------------- fused weight conversion (all 6 weights, one launch) ----------------
#define N_IP (4096 * 512)
#define N_XP (160 * 2048)
#define N_DT (2048 * 32)
#define N_OP (512 * 2048)
#define N_W1 (2048 * 512)
#define N_W2 (512 * 2048)
#define N_CVTW (N_IP + N_XP + N_DT + N_DT + N_OP + N_W1 + N_W2)   // + dt pad

__global__ void __launch_bounds__(256)
cvt_weights(const float* __restrict__ ipw, const float* __restrict__ xpw,
            const float* __restrict__ dtw, const float* __restrict__ opw,
            const float* __restrict__ w1,  const float* __restrict__ w2)
{
    int idx = blockIdx.x * 256 + threadIdx.x;
    if (idx < N_IP) { wsplit(ipw, idx, 512, 1536, g_wb + OFF_IP); return; }
    idx -= N_IP;
    if (idx < N_XP) { wsplit(xpw, idx, 2048, 6144, g_wb + OFF_XP); return; }
    idx -= N_XP;
    if (idx < N_DT) { wsplit(dtw, idx, 32, 128, g_wb + OFF_DT); return; }
    idx -= N_DT;
    if (idx < N_DT) {   // dt weight pad: cols [96,128) = 0
        int r = idx >> 5, k = idx & 31;
        g_wb[OFF_DT + (size_t)r * 128 + 96 + k] = __float2bfloat16(0.f);
        return;
    }
    idx -= N_DT;
    if (idx < N_OP) { wsplit(opw, idx, 2048, 6144, g_wb + OFF_OP); return; }
    idx -= N_OP;
    if (idx < N_W1) { wsplit(w1, idx, 512, 1536, g_wb + OFF_W1); return; }
    idx -= N_W1;
    if (idx < N_W2) { wsplit(w2, idx, 2048, 6144, g_wb + OFF_W2); }
}

// ---------------- dt activation conversion: xdbl[:, :32] -> actb2 3-plane K3p=128 ----------------
__global__ void __launch_bounds__(256)
cvt_dt_act()
{
    int i = blockIdx.x * 256 + threadIdx.x;
    if (i >= ROWS * 128) return;
    int r = i >> 7, c = i & 127;
    const float* src = g_xdbl + (size_t)r * XDBL;
    __nv_bfloat16 o;
    if (c < 32) o = __float2bfloat16(src[c]);
    else if (c < 64) {
        float a = src[c - 32];
        __nv_bfloat16 hi = __float2bfloat16(a);
        o = __float2bfloat16(a - __bfloat162float(hi));
    } else if (c < 96) o = __float2bfloat16(src[c - 64]);
    else o = __float2bfloat16(0.f);
    g_actb2[(size_t)r * 128 + c] = o;
}

#define APITCH 80                       // 32 bf16 (64B) + 16B pad

// ---------------- HMMA GEMM (narrow): BM=128, BN=64, 256 thr, warp tile 32x32 ----------------
// 4-stage cp.async pipeline, 1 barrier/chunk. EPI: 0 none
#define STAGE_BYTES (128 * APITCH + 64 * APITCH)   // 15360
#define SMEMSZ (4 * STAGE_BYTES)                    // 61440
template<int EPI>
__global__ void __launch_bounds__(256)
hmma_gemm(const __nv_bfloat16* __restrict__ A, const __nv_bfloat16* __restrict__ W,
          float* __restrict__ C, int N, int K3, int Ksl, size_t partStride,
          const float* __restrict__ bias, const float* __restrict__ resid)
{
    extern __shared__ __align__(16) char dsm[];

    const int tid = threadIdx.x;
    const int lane = tid & 31, wid = tid >> 5;
    const int warpM = (wid & 3) * 32;     // 4 warps along M
    const int warpN = (wid >> 2) * 32;    // 2 warps along N
    const int m0 = blockIdx.y * 128;
    const int n0 = blockIdx.x * 64;
    const int koff = blockIdx.z * Ksl;
    const int NC = Ksl / 32;
    C += (size_t)blockIdx.z * partStride;

    const uint32_t sbase = smem_u32(dsm);
    uint32_t aB[4], bB[4];
#pragma unroll
    for (int s = 0; s < 4; s++) { aB[s] = sbase + s * STAGE_BYTES; bB[s] = aB[s] + 128 * APITCH; }

    const int lr = tid >> 2, lseg = tid & 3;
    const uint32_t aLdOff = (uint32_t)((warpM + (lane & 15)) * APITCH + (lane >> 4) * 16);
    const uint32_t bLdOff = (uint32_t)((warpN + (lane & 7)) * APITCH + (lane >> 3) * 16);

    float acc[2][4][4];
#pragma unroll
    for (int i = 0; i < 2; i++)
#pragma unroll
        for (int j = 0; j < 4; j++)
#pragma unroll
            for (int q = 0; q < 4; q++) acc[i][j][q] = 0.f;

    auto load_chunk = [&](int buf, int c) {
        const __nv_bfloat16* asrc = A + (size_t)(m0 + lr) * K3 + koff + c * 32 + lseg * 8;
        cp16(aB[buf] + (uint32_t)(lr * APITCH + lseg * 16), asrc, 16);
        const __nv_bfloat16* asrc2 = asrc + (size_t)64 * K3;
        cp16(aB[buf] + (uint32_t)((lr + 64) * APITCH + lseg * 16), asrc2, 16);
        if (lr < 64) {
            int brow = n0 + lr;
            bool bv = (brow < N);
            const __nv_bfloat16* bsrc = W + (size_t)(bv ? brow : 0) * K3 + koff + c * 32 + lseg * 8;
            cp16(bB[buf] + (uint32_t)(lr * APITCH + lseg * 16), bsrc, bv ? 16 : 0);
        }
    };

    const int pf = NC < 3 ? NC : 3;
    for (int p = 0; p < pf; p++) { load_chunk(p, p); CP_COMMIT(); }

    for (int c = 0; c < NC; c++) {
        CP_WAIT2();
        __syncthreads();
        if (c + 3 < NC) { load_chunk((c + 3) & 3, c + 3); CP_COMMIT(); }
        const int buf = c & 3;

        uint32_t aF[2][2][4];
#pragma unroll
        for (int mt = 0; mt < 2; mt++)
#pragma unroll
            for (int kh = 0; kh < 2; kh++)
                ldsm4(aF[mt][kh][0], aF[mt][kh][1], aF[mt][kh][2], aF[mt][kh][3],
                      aB[buf] + aLdOff + (uint32_t)(mt * 16 * APITCH + kh * 32));
        uint32_t bF[4][4];
#pragma unroll
        for (int nt = 0; nt < 4; nt++)
            ldsm4(bF[nt][0], bF[nt][1], bF[nt][2], bF[nt][3],
                  bB[buf] + bLdOff + (uint32_t)(nt * 8 * APITCH));
#pragma unroll
        for (int kh = 0; kh < 2; kh++)
#pragma unroll
            for (int mt = 0; mt < 2; mt++)
#pragma unroll
                for (int nt = 0; nt < 4; nt++)
                    mma16816(acc[mt][nt], aF[mt][kh], &bF[nt][kh * 2]);
    }

    // ---- epilogue ----
#pragma unroll
    for (int mt = 0; mt < 2; mt++) {
        int row = m0 + warpM + mt * 16 + (lane >> 2);
#pragma unroll
        for (int nt = 0; nt < 4; nt++) {
            int col = n0 + warpN + nt * 8 + 2 * (lane & 3);
            if (col < N) {
                size_t i0 = (size_t)row * N + col;
                size_t i1 = (size_t)(row + 8) * N + col;
                *(float2*)&C[i0] = make_float2(acc[mt][nt][0], acc[mt][nt][1]);
                *(float2*)&C[i1] = make_float2(acc[mt][nt][2], acc[mt][nt][3]);
            }
        }
    }
}

// ---------------- HMMA GEMM (wide): BM=64, BN=128, 128 thr, warp tile 32x64 ----------------
// Requires N % 128 == 0 and M % 64 == 0 (in_proj, dt, w1). 3-stage pipeline.
// EPI: 0 none, 1 bias+softplus, 5 bias+gelu -> split-bf16 into g_actb2 (K=2048,K3p=6144)
#define STAGEW_BYTES (64 * APITCH + 128 * APITCH)  // 15360
#define SMEMSZW (3 * STAGEW_BYTES)                  // 46080
template<int EPI>
__global__ void __launch_bounds__(128)
hmma_gemmW(const __nv_bfloat16* __restrict__ A, const __nv_bfloat16* __restrict__ W,
           float* __restrict__ C, int N, int K3,
           const float* __restrict__ bias)
{
    extern __shared__ __align__(16) char dsm[];

    const int tid = threadIdx.x;
    const int lane = tid & 31, wid = tid >> 5;
    const int warpM = (wid & 1) * 32;     // 2 warps along M
    const int warpN = (wid >> 1) * 64;    // 2 warps along N
    const int m0 = blockIdx.y * 64;
    const int n0 = blockIdx.x * 128;
    const int NC = K3 / 32;

    const uint32_t sbase = smem_u32(dsm);
    uint32_t aB[3], bB[3];
#pragma unroll
    for (int s = 0; s < 3; s++) { aB[s] = sbase + s * STAGEW_BYTES; bB[s] = aB[s] + 64 * APITCH; }

    const int lr = tid >> 2, lseg = tid & 3;   // lr 0..31
    const uint32_t aLdOff = (uint32_t)((warpM + (lane & 15)) * APITCH + (lane >> 4) * 16);
    const uint32_t bLdOff = (uint32_t)((warpN + (lane & 7)) * APITCH + (lane >> 3) * 16);

    float acc[2][8][4];
#pragma unroll
    for (int i = 0; i < 2; i++)
#pragma unroll
        for (int j = 0; j < 8; j++)
#pragma unroll
            for (int q = 0; q < 4; q++) acc[i][j][q] = 0.f;

    auto load_chunk = [&](int buf, int c) {
        const __nv_bfloat16* asrc = A + (size_t)(m0 + lr) * K3 + c * 32 + lseg * 8;
        cp16(aB[buf] + (uint32_t)(lr * APITCH + lseg * 16), asrc, 16);
        cp16(aB[buf] + (uint32_t)((lr + 32) * APITCH + lseg * 16), asrc + (size_t)32 * K3, 16);
        const __nv_bfloat16* bsrc = W + (size_t)(n0 + lr) * K3 + c * 32 + lseg * 8;
        cp16(bB[buf] + (uint32_t)(lr * APITCH + lseg * 16), bsrc, 16);
        cp16(bB[buf] + (uint32_t)((lr + 32) * APITCH + lseg * 16), bsrc + (size_t)32 * K3, 16);
        cp16(bB[buf] + (uint32_t)((lr + 64) * APITCH + lseg * 16), bsrc + (size_t)64 * K3, 16);
        cp16(bB[buf] + (uint32_t)((lr + 96) * APITCH + lseg * 16), bsrc + (size_t)96 * K3, 16);
    };

    const int pf = NC < 2 ? NC : 2;
    for (int p = 0; p < pf; p++) { load_chunk(p, p); CP_COMMIT(); }

    for (int c = 0; c < NC; c++) {
        CP_WAIT1();
        __syncthreads();
        if (c + 2 < NC) { load_chunk((c + 2) % 3, c + 2); CP_COMMIT(); }
        const int buf = c % 3;

        uint32_t aF[2][2][4];
#pragma unroll
        for (int mt = 0; mt < 2; mt++)
#pragma unroll
            for (int kh = 0; kh < 2; kh++)
                ldsm4(aF[mt][kh][0], aF[mt][kh][1], aF[mt][kh][2], aF[mt][kh][3],
                      aB[buf] + aLdOff + (uint32_t)(mt * 16 * APITCH + kh * 32));
#pragma unroll
        for (int half = 0; half < 2; half++) {
            uint32_t bF[4][4];
#pragma unroll
            for (int j = 0; j < 4; j++)
                ldsm4(bF[j][0], bF[j][1], bF[j][2], bF[j][3],
                      bB[buf] + bLdOff + (uint32_t)((half * 4 + j) * 8 * APITCH));
#pragma unroll
            for (int kh = 0; kh < 2; kh++)
#pragma unroll
                for (int mt = 0; mt < 2; mt++)
#pragma unroll
                    for (int j = 0; j < 4; j++)
                        mma16816(acc[mt][half * 4 + j], aF[mt][kh], &bF[j][kh * 2]);
        }
    }

    // ---- epilogue ----
#pragma unroll
    for (int mt = 0; mt < 2; mt++) {
        int row = m0 + warpM + mt * 16 + (lane >> 2);
#pragma unroll
        for (int nt = 0; nt < 8; nt++) {
            int col = n0 + warpN + nt * 8 + 2 * (lane & 3);
            float v0 = acc[mt][nt][0], v1 = acc[mt][nt][1];
            float v2 = acc[mt][nt][2], v3 = acc[mt][nt][3];
            if (EPI == 1) {
                float b0 = bias[col], b1 = bias[col + 1];
                v0 = softplusf_(v0 + b0); v1 = softplusf_(v1 + b1);
                v2 = softplusf_(v2 + b0); v3 = softplusf_(v3 + b1);
            } else if (EPI == 5) {
                float b0 = bias[col], b1 = bias[col + 1];
                v0 = geluf_(v0 + b0); v1 = geluf_(v1 + b1);
                v2 = geluf_(v2 + b0); v3 = geluf_(v3 + b1);
            }
            if (EPI == 5) {
                size_t rb0 = (size_t)row * 6144;
                size_t rb1 = (size_t)(row + 8) * 6144;
                split_store3(g_actb2, rb0, col,     2048, v0);
                split_store3(g_actb2, rb0, col + 1, 2048, v1);
                split_store3(g_actb2, rb1, col,     2048, v2);
                split_store3(g_actb2, rb1, col + 1, 2048, v3);
            } else {
                *(float2*)&C[(size_t)row * N + col]       = make_float2(v0, v1);
                *(float2*)&C[(size_t)(row + 8) * N + col] = make_float2(v2, v3);
            }
        }
    }
}

// ---------------- split-K reduce (+epilogue). REPI: 0 sum, 2 sum+resid, 4 sum+bias+resid
template<int REPI>
__global__ void __launch_bounds__(256)
reduce_kernel(const float* __restrict__ part, float* __restrict__ out,
              int total4, int slices, size_t partStride, int ldc,
              const float* __restrict__ bias, const float* __restrict__ resid)
{
    int i = blockIdx.x * 256 + threadIdx.x;
    if (i >= total4) return;
    size_t e = (size_t)i * 4;
    float4 acc = *(const float4*)(part + e);
    for (int s = 1; s < slices; s++) {
        float4 v = *(const float4*)(part + (size_t)s * partStride + e);
        acc.x += v.x; acc.y += v.y; acc.z += v.z; acc.w += v.w;
    }
    if (REPI >= 4) {
        int n = (int)(e % ldc);
        acc.x += bias[n]; acc.y += bias[n + 1]; acc.z += bias[n + 2]; acc.w += bias[n + 3];
    }
    if (REPI >= 2) {
        float4 r = *(const float4*)(resid + e);
        acc.x += r.x; acc.y += r.y; acc.z += r.z; acc.w += r.w;
    }
    *(float4*)(out + e) = acc;
}

// ---------------- depthwise causal conv (D_CONV=4) + SiLU; writes u fp32 + split-bf16 ----------------
__global__ void __launch_bounds__(256)
conv_silu_kernel(const float* __restrict__ cw, const float* __restrict__ cb)
{
    int gid = blockIdx.x * 256 + threadIdx.x;   // over ROWS*DIN
    int d = gid & (DIN - 1);
    int row = gid >> 11;
    int t = row & (LL - 1);
    float acc = cb[d];
    const float* base = g_xz + (size_t)row * (2 * DIN) + d;
#pragma unroll
    for (int k = 0; k < DCONV; k++) {
        int off = k - (DCONV - 1);
        if (t + off >= 0)
            acc = fmaf(cw[d * DCONV + k], base[(long)off * (2 * DIN)], acc);
    }
    float s = acc * sigmoidf_(acc);
    g_u[gid] = s;
    split_store3(g_actb, (size_t)row * 6144, d, DIN, s);
}

// ---------------- selective scan v2: warp per (b,d) channel ----------------
#define GD 8
#define CT 32

__global__ void __launch_bounds__(256)
scan_kernel(const float* __restrict__ A_log, const float* __restrict__ Dw)
{
    __shared__ float sB[CT][DSTATE];
    __shared__ float sC[CT][DSTATE];
    __shared__ float sdt[CT][GD];
    __shared__ float su [CT][GD];
    __shared__ float sz [CT][GD];
    __shared__ float sp [GD][CT][33];

    const int tid = threadIdx.x;
    const int w = tid >> 5, lane = tid & 31;
    const int b = blockIdx.y;
    const int d0 = blockIdx.x * GD;
    const int d = d0 + w;

    const float L2E = 1.44269504f;
    const float a0 = -__expf(A_log[d * DSTATE + 2 * lane])     * L2E;
    const float a1 = -__expf(A_log[d * DSTATE + 2 * lane + 1]) * L2E;
    const float Dd = Dw[d];
    float h0 = 0.f, h1 = 0.f;

    const float* xdbl_b = g_xdbl + (size_t)b * LL * XDBL;
    const float* dt_b = g_dt + (size_t)b * LL * DIN + d0;
    const float* u_b  = g_u  + (size_t)b * LL * DIN + d0;
    const float* z_b  = g_xz + (size_t)b * LL * (2 * DIN) + DIN + d0;

    for (int t0 = 0; t0 < LL; t0 += CT) {
        __syncthreads();
#pragma unroll
        for (int r = 0; r < (CT * DSTATE) / 256; r++) {
            int e = tid + r * 256;
            int tt = e >> 6, n = e & 63;
            const float* src = xdbl_b + (size_t)(t0 + tt) * XDBL + DTRANK;
            sB[tt][n] = src[n];
            sC[tt][n] = src[DSTATE + n];
        }
        {
            int tt = tid >> 3, dd = tid & 7;
            sdt[tt][dd] = dt_b[(size_t)(t0 + tt) * DIN + dd];
            su [tt][dd] = u_b [(size_t)(t0 + tt) * DIN + dd];
            sz [tt][dd] = z_b [(size_t)(t0 + tt) * (2 * DIN) + dd];
        }
        __syncthreads();
#pragma unroll 8
        for (int tt = 0; tt < CT; tt++) {
            float dtv = sdt[tt][w], uv = su[tt][w];
            float2 Bv = *(const float2*)&sB[tt][2 * lane];
            float2 Cv = *(const float2*)&sC[tt][2 * lane];
            float dA0 = ex2_(dtv * a0);
            float dA1 = ex2_(dtv * a1);
            float du = dtv * uv;
            h0 = fmaf(dA0, h0, du * Bv.x);
            h1 = fmaf(dA1, h1, du * Bv.y);
            sp[w][tt][lane] = fmaf(h1, Cv.y, h0 * Cv.x);
        }
        __syncwarp();
        {
            const float* pr = &sp[w][lane][0];
            float sum = 0.f;
#pragma unroll
            for (int i = 0; i < 32; i++) sum += pr[i];
            float uvv = su[lane][w];
            float zvv = sz[lane][w];
            float yv = fmaf(uvv, Dd, sum);
            float o = yv * (zvv * sigmoidf_(zvv));
            split_store3(g_actb, (size_t)(b * LL + t0 + lane) * 6144, d, DIN, o);
        }
    }
}

// ---------------- launch ----------------
static inline int cdiv(int a, int b) { return (a + b - 1) / b; }

extern "C" void kernel_launch(void* const* d_in, const int* in_sizes, int n_in,
                              void* d_out, int out_size)
{
    const float* x         = (const float*)d_in[0];
    const float* ln1_g     = (const float*)d_in[1];
    const float* ln1_b     = (const float*)d_in[2];
    const float* in_proj_w = (const float*)d_in[3];
    const float* conv_w    = (const float*)d_in[4];
    const float* conv_b    = (const float*)d_in[5];
    const float* x_proj_w  = (const float*)d_in[6];
    const float* dt_w      = (const float*)d_in[7];
    const float* dt_b      = (const float*)d_in[8];
    const float* A_log     = (const float*)d_in[9];
    const float* D         = (const float*)d_in[10];
    const float* out_proj_w= (const float*)d_in[11];
    const float* ln2_g     = (const float*)d_in[12];
    const float* ln2_b     = (const float*)d_in[13];
    const float* w1        = (const float*)d_in[14];
    const float* b1        = (const float*)d_in[15];
    const float* w2        = (const float*)d_in[16];
    const float* b2        = (const float*)d_in[17];
    float* out = (float*)d_out;

    float *xz, *u, *xdbl, *dt, *x2, *part;
    __nv_bfloat16 *actb, *actb2, *wb;
    cudaGetSymbolAddress((void**)&xz,   g_xz);
    cudaGetSymbolAddress((void**)&u,    g_u);
    cudaGetSymbolAddress((void**)&xdbl, g_xdbl);
    cudaGetSymbolAddress((void**)&dt,   g_dt);
    cudaGetSymbolAddress((void**)&x2,   g_x2);
    cudaGetSymbolAddress((void**)&part, g_part);
    cudaGetSymbolAddress((void**)&actb, g_actb);
    cudaGetSymbolAddress((void**)&actb2,g_actb2);
    cudaGetSymbolAddress((void**)&wb,   g_wb);

    cudaFuncSetAttribute(hmma_gemm<0>,  cudaFuncAttributeMaxDynamicSharedMemorySize, SMEMSZ);
    cudaFuncSetAttribute(hmma_gemmW<0>, cudaFuncAttributeMaxDynamicSharedMemorySize, SMEMSZW);
    cudaFuncSetAttribute(hmma_gemmW<1>, cudaFuncAttributeMaxDynamicSharedMemorySize, SMEMSZW);
    cudaFuncSetAttribute(hmma_gemmW<5>, cudaFuncAttributeMaxDynamicSharedMemorySize, SMEMSZW);

    // 0. all weight conversions (one launch)
    cvt_weights<<<cdiv(N_CVTW, 256), 256>>>(in_proj_w, x_proj_w, dt_w, out_proj_w, w1, w2);

    // 1. LN1 -> actb (split-bf16, K3p=1536)
    ln_kernel<<<ROWS, 128>>>(x, ln1_g, ln1_b, actb, 1e-5f);

    // 2. in_proj: xz = y @ in_proj_w^T  [2048 x 4096], K3=1536  (wide kernel)
    hmma_gemmW<0><<<dim3(32, 32), 128, SMEMSZW>>>(actb, wb + OFF_IP, xz, 2 * DIN, 1536, nullptr);

    // 3. causal conv + silu -> u (fp32) + actb (split-bf16, K3p=6144)
    conv_silu_kernel<<<(ROWS * DIN) / 256, 256>>>(conv_w, conv_b);

    // 4. x_proj: xdbl = u @ x_proj_w^T  [2048 x 160], K3=6144, split-K=8 (narrow kernel)
    hmma_gemm<0><<<dim3(3, 16, 8), 256, SMEMSZ>>>(actb, wb + OFF_XP, part, XDBL, 6144, 768,
                                                  (size_t)ROWS * XDBL, nullptr, nullptr);
    reduce_kernel<0><<<(ROWS * XDBL / 4 + 255) / 256, 256>>>(part, xdbl, ROWS * XDBL / 4, 8,
                                                             (size_t)ROWS * XDBL, XDBL, nullptr, nullptr);

    // 5. dt = softplus(xdbl[:, :32] @ dt_w^T + dt_b)  [2048 x 2048], K3p=128 (wide kernel)
    cvt_dt_act<<<cdiv(ROWS * 128, 256), 256>>>();
    hmma_gemmW<1><<<dim3(16, 32), 128, SMEMSZW>>>(actb2, wb + OFF_DT, dt, DIN, 128, dt_b);

    // 6. selective scan -> actb (split-bf16, K3p=6144)
    scan_kernel<<<dim3(DIN / GD, BB), 256>>>(A_log, D);

    // 7. out_proj: x2 = x + ys @ out_proj_w^T  [2048 x 512], K3=6144, split-K=3 (narrow)
    hmma_gemm<0><<<dim3(8, 16, 3), 256, SMEMSZ>>>(actb, wb + OFF_OP, part, DIM, 6144, 2048,
                                                  (size_t)ROWS * DIM, nullptr, nullptr);
    reduce_kernel<2><<<(ROWS * DIM / 4 + 255) / 256, 256>>>(part, x2, ROWS * DIM / 4, 3,
                                                            (size_t)ROWS * DIM, DIM, nullptr, x);

    // 8. LN2 -> actb (split-bf16, K3p=1536)
    ln_kernel<<<ROWS, 128>>>(x2, ln2_g, ln2_b, actb, 1e-6f);

    // 9. h1 = gelu(y2 @ w1^T + b1) -> actb2 (split-bf16, K3p=6144)  [2048 x 2048], K3=1536 (wide)
    hmma_gemmW<5><<<dim3(16, 32), 128, SMEMSZW>>>(actb, wb + OFF_W1, nullptr, 4 * DIM, 1536, b1);

    // 10. out = x2 + h1 @ w2^T + b2  [2048 x 512], K3=6144, split-K=3 (narrow)
    hmma_gemm<0><<<dim3(8, 16, 3), 256, SMEMSZ>>>(actb2, wb + OFF_W2, part, DIM, 6144, 2048,
                                                  (size_t)ROWS * DIM, nullptr, nullptr);
    reduce_kernel<4><<<(ROWS * DIM / 4 + 255) / 256, 256>>>(part, out, ROWS * DIM / 4, 3,
                                                            (size_t)ROWS * DIM, DIM, b2, x2);
}

// round 11
// speedup vs baseline: 1.1064x; 1.0022x over previous
#include <cuda_runtime.h>
#include <cuda_bf16.h>
#include <math.h>
#include <stdint.h>

#define BB 2
#define LL 1024
#define DIM 512
#define DSTATE 64
#define DCONV 4
#define DIN 2048
#define DTRANK 32
#define XDBL 160            // DT_RANK + 2*D_STATE
#define ROWS 2048           // B*L

// weight-plane regions inside g_wb (split-bf16, K3p layout)
#define OFF_IP 0                    // in_proj : 4096 x 1536
#define OFF_XP 6291456              // x_proj  : 160  x 6144
#define OFF_DT 7274496              // dt      : 2048 x 128
#define OFF_OP 7536640              // out_proj: 512  x 6144
#define OFF_W1 10682368             // w1      : 2048 x 1536
#define OFF_W2 13828096             // w2      : 512  x 6144
#define WB_TOTAL 16973824

// ---------------- scratch (device globals; no allocs allowed) ----------------
static __device__ __align__(16) float g_xz  [ROWS * 2 * DIN];
static __device__ __align__(16) float g_u   [ROWS * DIN];
static __device__ __align__(16) float g_xdbl[ROWS * XDBL];
static __device__ __align__(16) float g_dt  [ROWS * DIN];
static __device__ __align__(16) float g_x2  [ROWS * DIM];
static __device__ __align__(16) float g_part[8 * ROWS * DIM];                    // split-K partials
static __device__ __align__(16) __nv_bfloat16 g_actb [ROWS * 6144];              // A' split-bf16
static __device__ __align__(16) __nv_bfloat16 g_actb2[ROWS * 6144];              // A' (2nd, for MLP/dt)
static __device__ __align__(16) __nv_bfloat16 g_wb  [WB_TOTAL];                  // W' split-bf16 (all 6)

// ---------------- math helpers ----------------
__device__ __forceinline__ float sigmoidf_(float x) { return __fdividef(1.f, 1.f + __expf(-x)); }
__device__ __forceinline__ float softplusf_(float x){ return x > 20.f ? x : log1pf(__expf(x)); }
__device__ __forceinline__ float geluf_(float x)    { return 0.5f * x * (1.f + erff(x * 0.70710678118654752f)); }
__device__ __forceinline__ float ex2_(float x) {
    float r; asm("ex2.approx.f32 %0, %1;" : "=f"(r) : "f"(x)); return r;
}

__device__ __forceinline__ void split_store3(__nv_bfloat16* base, size_t rb, int k, int K, float v) {
    __nv_bfloat16 hi = __float2bfloat16(v);
    __nv_bfloat16 lo = __float2bfloat16(v - __bfloat162float(hi));
    base[rb + k] = hi; base[rb + K + k] = lo; base[rb + 2 * K + k] = hi;
}

// weight mode: [0,K)=hi [K,2K)=hi [2K,3K)=lo
__device__ __forceinline__ void wsplit(const float* __restrict__ src, int idx, int K, int K3p,
                                       __nv_bfloat16* __restrict__ dst) {
    int r = idx / K, k = idx - r * K;
    float a = src[(size_t)r * K + k];
    __nv_bfloat16 hi = __float2bfloat16(a);
    __nv_bfloat16 lo = __float2bfloat16(a - __bfloat162float(hi));
    __nv_bfloat16* dr = dst + (size_t)r * K3p;
    dr[k] = hi; dr[K + k] = hi; dr[2 * K + k] = lo;
}

// ---------------- PTX helpers (baseline ISA only: sm_80+, valid on sm_103) ----------------
__device__ __forceinline__ uint32_t smem_u32(const void* p) {
    uint32_t a;
    asm("{ .reg .u64 t; cvta.to.shared.u64 t, %1; cvt.u32.u64 %0, t; }" : "=r"(a) : "l"(p));
    return a;
}
__device__ __forceinline__ void cp16(uint32_t dst, const void* src, int srcsize) {
    asm volatile("cp.async.cg.shared.global [%0], [%1], 16, %2;" :: "r"(dst), "l"(src), "r"(srcsize) : "memory");
}
#define CP_COMMIT() asm volatile("cp.async.commit_group;" ::: "memory")
#define CP_WAIT2()  asm volatile("cp.async.wait_group 2;" ::: "memory")
#define CP_WAIT1()  asm volatile("cp.async.wait_group 1;" ::: "memory")

__device__ __forceinline__ void ldsm4(uint32_t& r0, uint32_t& r1, uint32_t& r2, uint32_t& r3, uint32_t addr) {
    asm volatile("ldmatrix.sync.aligned.m8n8.x4.shared.b16 {%0,%1,%2,%3}, [%4];"
                 : "=r"(r0), "=r"(r1), "=r"(r2), "=r"(r3) : "r"(addr));
}
__device__ __forceinline__ void mma16816(float* c, const uint32_t* a, const uint32_t* b) {
    asm volatile("mma.sync.aligned.m16n8k16.row.col.f32.bf16.bf16.f32 "
                 "{%0,%1,%2,%3}, {%4,%5,%6,%7}, {%8,%9}, {%0,%1,%2,%3};"
                 : "+f"(c[0]), "+f"(c[1]), "+f"(c[2]), "+f"(c[3])
                 : "r"(a[0]), "r"(a[1]), "r"(a[2]), "r"(a[3]), "r"(b[0]), "r"(b[1]));
}

// ---------------- LayerNorm (writes split-bf16 3-plane directly, K=512 -> K3p=1536) ----------------
__global__ void __launch_bounds__(128)
ln_kernel(const float* __restrict__ x, const float* __restrict__ g,
          const float* __restrict__ b, __nv_bfloat16* __restrict__ outb, float eps)
{
    int row = blockIdx.x;
    const float* xr = x + (size_t)row * DIM;
    float v[4];
    float s = 0.f;
#pragma unroll
    for (int i = 0; i < 4; i++) { v[i] = xr[threadIdx.x + i * 128]; s += v[i]; }
    __shared__ float red[8];
#pragma unroll
    for (int o = 16; o > 0; o >>= 1) s += __shfl_xor_sync(0xffffffffu, s, o);
    if ((threadIdx.x & 31) == 0) red[threadIdx.x >> 5] = s;
    __syncthreads();
    float mean = (red[0] + red[1] + red[2] + red[3]) * (1.f / DIM);
    float s2 = 0.f;
#pragma unroll
    for (int i = 0; i < 4; i++) { float d = v[i] - mean; s2 += d * d; }
#pragma unroll
    for (int o = 16; o > 0; o >>= 1) s2 += __shfl_xor_sync(0xffffffffu, s2, o);
    if ((threadIdx.x & 31) == 0) red[4 + (threadIdx.x >> 5)] = s2;
    __syncthreads();
    float var = (red[4] + red[5] + red[6] + red[7]) * (1.f / DIM);
    float rstd = rsqrtf(var + eps);
    size_t rb = (size_t)row * 1536;
#pragma unroll
    for (int i = 0; i < 4; i++) {
        int c = threadIdx.x + i * 128;
        float o = (v[i] - mean) * rstd * g[c] + b[c];
        split_store3(outb, rb, c, DIM, o);
    }
}

// ---------------- weight conversion: in_proj only (launch #2) ----------------
#define N_IP (4096 * 512)
#define N_XP (160 * 2048)
#define N_DT (2048 * 32)
#define N_OP (512 * 2048)
#define N_W1 (2048 * 512)
#define N_W2 (512 * 2048)
#define N_CVTR (N_XP + N_DT + N_DT + N_OP + N_W1 + N_W2)

__global__ void __launch_bounds__(256)
cvt_wip(const float* __restrict__ ipw)
{
    int idx = blockIdx.x * 256 + threadIdx.x;
    if (idx < N_IP) wsplit(ipw, idx, 512, 1536, g_wb + OFF_IP);
}

// ---------------- weight conversion: the rest (launch #3) ----------------
__global__ void __launch_bounds__(256)
cvt_wrest(const float* __restrict__ xpw, const float* __restrict__ dtw,
          const float* __restrict__ opw, const float* __restrict__ w1,
          const float* __restrict__ w2)
{
    int idx = blockIdx.x * 256 + threadIdx.x;
    if (idx < N_XP) { wsplit(xpw, idx, 2048, 6144, g_wb + OFF_XP); return; }
    idx -= N_XP;
    if (idx < N_DT) { wsplit(dtw, idx, 32, 128, g_wb + OFF_DT); return; }
    idx -= N_DT;
    if (idx < N_DT) {   // dt weight pad: cols [96,128) = 0
        int r = idx >> 5, k = idx & 31;
        g_wb[OFF_DT + (size_t)r * 128 + 96 + k] = __float2bfloat16(0.f);
        return;
    }
    idx -= N_DT;
    if (idx < N_OP) { wsplit(opw, idx, 2048, 6144, g_wb + OFF_OP); return; }
    idx -= N_OP;
    if (idx < N_W1) { wsplit(w1, idx, 512, 1536, g_wb + OFF_W1); return; }
    idx -= N_W1;
    if (idx < N_W2) { wsplit(w2, idx, 2048, 6144, g_wb + OFF_W2); }
}

#define APITCH 80                       // 32 bf16 (64B) + 16B pad

// ---------------- HMMA GEMM (narrow): BM=128, BN=64, 256 thr, warp tile 32x32 ----------------
// Used only for x_proj (N=160). 4-stage, split-K.
#define STAGE_BYTES (128 * APITCH + 64 * APITCH)   // 15360
#define SMEMSZ (4 * STAGE_BYTES)                    // 61440
__global__ void __launch_bounds__(256)
hmma_gemm(const __nv_bfloat16* __restrict__ A, const __nv_bfloat16* __restrict__ W,
          float* __restrict__ C, int N, int K3, int Ksl, size_t partStride)
{
    extern __shared__ __align__(16) char dsm[];

    const int tid = threadIdx.x;
    const int lane = tid & 31, wid = tid >> 5;
    const int warpM = (wid & 3) * 32;
    const int warpN = (wid >> 2) * 32;
    const int m0 = blockIdx.y * 128;
    const int n0 = blockIdx.x * 64;
    const int koff = blockIdx.z * Ksl;
    const int NC = Ksl / 32;
    C += (size_t)blockIdx.z * partStride;

    const uint32_t sbase = smem_u32(dsm);
    uint32_t aB[4], bB[4];
#pragma unroll
    for (int s = 0; s < 4; s++) { aB[s] = sbase + s * STAGE_BYTES; bB[s] = aB[s] + 128 * APITCH; }

    const int lr = tid >> 2, lseg = tid & 3;
    const uint32_t aLdOff = (uint32_t)((warpM + (lane & 15)) * APITCH + (lane >> 4) * 16);
    const uint32_t bLdOff = (uint32_t)((warpN + (lane & 7)) * APITCH + (lane >> 3) * 16);

    float acc[2][4][4];
#pragma unroll
    for (int i = 0; i < 2; i++)
#pragma unroll
        for (int j = 0; j < 4; j++)
#pragma unroll
            for (int q = 0; q < 4; q++) acc[i][j][q] = 0.f;

    auto load_chunk = [&](int buf, int c) {
        const __nv_bfloat16* asrc = A + (size_t)(m0 + lr) * K3 + koff + c * 32 + lseg * 8;
        cp16(aB[buf] + (uint32_t)(lr * APITCH + lseg * 16), asrc, 16);
        const __nv_bfloat16* asrc2 = asrc + (size_t)64 * K3;
        cp16(aB[buf] + (uint32_t)((lr + 64) * APITCH + lseg * 16), asrc2, 16);
        if (lr < 64) {
            int brow = n0 + lr;
            bool bv = (brow < N);
            const __nv_bfloat16* bsrc = W + (size_t)(bv ? brow : 0) * K3 + koff + c * 32 + lseg * 8;
            cp16(bB[buf] + (uint32_t)(lr * APITCH + lseg * 16), bsrc, bv ? 16 : 0);
        }
    };

    const int pf = NC < 3 ? NC : 3;
    for (int p = 0; p < pf; p++) { load_chunk(p, p); CP_COMMIT(); }

    for (int c = 0; c < NC; c++) {
        CP_WAIT2();
        __syncthreads();
        if (c + 3 < NC) { load_chunk((c + 3) & 3, c + 3); CP_COMMIT(); }
        const int buf = c & 3;

        uint32_t aF[2][2][4];
#pragma unroll
        for (int mt = 0; mt < 2; mt++)
#pragma unroll
            for (int kh = 0; kh < 2; kh++)
                ldsm4(aF[mt][kh][0], aF[mt][kh][1], aF[mt][kh][2], aF[mt][kh][3],
                      aB[buf] + aLdOff + (uint32_t)(mt * 16 * APITCH + kh * 32));
        uint32_t bF[4][4];
#pragma unroll
        for (int nt = 0; nt < 4; nt++)
            ldsm4(bF[nt][0], bF[nt][1], bF[nt][2], bF[nt][3],
                  bB[buf] + bLdOff + (uint32_t)(nt * 8 * APITCH));
#pragma unroll
        for (int kh = 0; kh < 2; kh++)
#pragma unroll
            for (int mt = 0; mt < 2; mt++)
#pragma unroll
                for (int nt = 0; nt < 4; nt++)
                    mma16816(acc[mt][nt], aF[mt][kh], &bF[nt][kh * 2]);
    }

#pragma unroll
    for (int mt = 0; mt < 2; mt++) {
        int row = m0 + warpM + mt * 16 + (lane >> 2);
#pragma unroll
        for (int nt = 0; nt < 4; nt++) {
            int col = n0 + warpN + nt * 8 + 2 * (lane & 3);
            if (col < N) {
                *(float2*)&C[(size_t)row * N + col]       = make_float2(acc[mt][nt][0], acc[mt][nt][1]);
                *(float2*)&C[(size_t)(row + 8) * N + col] = make_float2(acc[mt][nt][2], acc[mt][nt][3]);
            }
        }
    }
}

// ---------------- HMMA GEMM (wide): BM=64, BN=128, 128 thr, warp tile 32x64 ----------------
// Requires N % 128 == 0 and M % 64 == 0. 3-stage pipeline, split-K capable.
// EPI: 0 none, 1 bias+softplus, 5 bias+gelu -> split-bf16 into g_actb2 (K=2048,K3p=6144)
#define STAGEW_BYTES (64 * APITCH + 128 * APITCH)  // 15360
#define SMEMSZW (3 * STAGEW_BYTES)                  // 46080
template<int EPI>
__global__ void __launch_bounds__(128)
hmma_gemmW(const __nv_bfloat16* __restrict__ A, const __nv_bfloat16* __restrict__ W,
           float* __restrict__ C, int N, int K3, int Ksl, size_t partStride,
           const float* __restrict__ bias)
{
    extern __shared__ __align__(16) char dsm[];

    const int tid = threadIdx.x;
    const int lane = tid & 31, wid = tid >> 5;
    const int warpM = (wid & 1) * 32;
    const int warpN = (wid >> 1) * 64;
    const int m0 = blockIdx.y * 64;
    const int n0 = blockIdx.x * 128;
    const int koff = blockIdx.z * Ksl;
    const int NC = Ksl / 32;
    C += (size_t)blockIdx.z * partStride;

    const uint32_t sbase = smem_u32(dsm);
    uint32_t aB[3], bB[3];
#pragma unroll
    for (int s = 0; s < 3; s++) { aB[s] = sbase + s * STAGEW_BYTES; bB[s] = aB[s] + 64 * APITCH; }

    const int lr = tid >> 2, lseg = tid & 3;   // lr 0..31
    const uint32_t aLdOff = (uint32_t)((warpM + (lane & 15)) * APITCH + (lane >> 4) * 16);
    const uint32_t bLdOff = (uint32_t)((warpN + (lane & 7)) * APITCH + (lane >> 3) * 16);

    float acc[2][8][4];
#pragma unroll
    for (int i = 0; i < 2; i++)
#pragma unroll
        for (int j = 0; j < 8; j++)
#pragma unroll
            for (int q = 0; q < 4; q++) acc[i][j][q] = 0.f;

    auto load_chunk = [&](int buf, int c) {
        const __nv_bfloat16* asrc = A + (size_t)(m0 + lr) * K3 + koff + c * 32 + lseg * 8;
        cp16(aB[buf] + (uint32_t)(lr * APITCH + lseg * 16), asrc, 16);
        cp16(aB[buf] + (uint32_t)((lr + 32) * APITCH + lseg * 16), asrc + (size_t)32 * K3, 16);
        const __nv_bfloat16* bsrc = W + (size_t)(n0 + lr) * K3 + koff + c * 32 + lseg * 8;
        cp16(bB[buf] + (uint32_t)(lr * APITCH + lseg * 16), bsrc, 16);
        cp16(bB[buf] + (uint32_t)((lr + 32) * APITCH + lseg * 16), bsrc + (size_t)32 * K3, 16);
        cp16(bB[buf] + (uint32_t)((lr + 64) * APITCH + lseg * 16), bsrc + (size_t)64 * K3, 16);
        cp16(bB[buf] + (uint32_t)((lr + 96) * APITCH + lseg * 16), bsrc + (size_t)96 * K3, 16);
    };

    const int pf = NC < 2 ? NC : 2;
    for (int p = 0; p < pf; p++) { load_chunk(p, p); CP_COMMIT(); }

    for (int c = 0; c < NC; c++) {
        CP_WAIT1();
        __syncthreads();
        if (c + 2 < NC) { load_chunk((c + 2) % 3, c + 2); CP_COMMIT(); }
        const int buf = c % 3;

        uint32_t aF[2][2][4];
#pragma unroll
        for (int mt = 0; mt < 2; mt++)
#pragma unroll
            for (int kh = 0; kh < 2; kh++)
                ldsm4(aF[mt][kh][0], aF[mt][kh][1], aF[mt][kh][2], aF[mt][kh][3],
                      aB[buf] + aLdOff + (uint32_t)(mt * 16 * APITCH + kh * 32));
#pragma unroll
        for (int half = 0; half < 2; half++) {
            uint32_t bF[4][4];
#pragma unroll
            for (int j = 0; j < 4; j++)
                ldsm4(bF[j][0], bF[j][1], bF[j][2], bF[j][3],
                      bB[buf] + bLdOff + (uint32_t)((half * 4 + j) * 8 * APITCH));
#pragma unroll
            for (int kh = 0; kh < 2; kh++)
#pragma unroll
                for (int mt = 0; mt < 2; mt++)
#pragma unroll
                    for (int j = 0; j < 4; j++)
                        mma16816(acc[mt][half * 4 + j], aF[mt][kh], &bF[j][kh * 2]);
        }
    }

    // ---- epilogue ----
#pragma unroll
    for (int mt = 0; mt < 2; mt++) {
        int row = m0 + warpM + mt * 16 + (lane >> 2);
#pragma unroll
        for (int nt = 0; nt < 8; nt++) {
            int col = n0 + warpN + nt * 8 + 2 * (lane & 3);
            float v0 = acc[mt][nt][0], v1 = acc[mt][nt][1];
            float v2 = acc[mt][nt][2], v3 = acc[mt][nt][3];
            if (EPI == 1) {
                float b0 = bias[col], b1 = bias[col + 1];
                v0 = softplusf_(v0 + b0); v1 = softplusf_(v1 + b1);
                v2 = softplusf_(v2 + b0); v3 = softplusf_(v3 + b1);
            } else if (EPI == 5) {
                float b0 = bias[col], b1 = bias[col + 1];
                v0 = geluf_(v0 + b0); v1 = geluf_(v1 + b1);
                v2 = geluf_(v2 + b0); v3 = geluf_(v3 + b1);
            }
            if (EPI == 5) {
                size_t rb0 = (size_t)row * 6144;
                size_t rb1 = (size_t)(row + 8) * 6144;
                split_store3(g_actb2, rb0, col,     2048, v0);
                split_store3(g_actb2, rb0, col + 1, 2048, v1);
                split_store3(g_actb2, rb1, col,     2048, v2);
                split_store3(g_actb2, rb1, col + 1, 2048, v3);
            } else {
                *(float2*)&C[(size_t)row * N + col]       = make_float2(v0, v1);
                *(float2*)&C[(size_t)(row + 8) * N + col] = make_float2(v2, v3);
            }
        }
    }
}

// ---------------- split-K reduce (+epilogue). REPI: 2 sum+resid, 4 sum+bias+resid ----------------
template<int REPI>
__global__ void __launch_bounds__(256)
reduce_kernel(const float* __restrict__ part, float* __restrict__ out,
              int total4, int slices, size_t partStride, int ldc,
              const float* __restrict__ bias, const float* __restrict__ resid)
{
    int i = blockIdx.x * 256 + threadIdx.x;
    if (i >= total4) return;
    size_t e = (size_t)i * 4;
    float4 acc = *(const float4*)(part + e);
    for (int s = 1; s < slices; s++) {
        float4 v = *(const float4*)(part + (size_t)s * partStride + e);
        acc.x += v.x; acc.y += v.y; acc.z += v.z; acc.w += v.w;
    }
    if (REPI >= 4) {
        int n = (int)(e % ldc);
        acc.x += bias[n]; acc.y += bias[n + 1]; acc.z += bias[n + 2]; acc.w += bias[n + 3];
    }
    if (REPI >= 2) {
        float4 r = *(const float4*)(resid + e);
        acc.x += r.x; acc.y += r.y; acc.z += r.z; acc.w += r.w;
    }
    *(float4*)(out + e) = acc;
}

// ---------------- x_proj reduce fused with dt-activation 3-plane conversion ----------------
__global__ void __launch_bounds__(256)
reduce_xp()
{
    const int total4 = ROWS * XDBL / 4;
    int i = blockIdx.x * 256 + threadIdx.x;
    if (i >= total4) return;
    size_t e = (size_t)i * 4;
    const float* part = g_part;
    float4 acc = *(const float4*)(part + e);
#pragma unroll
    for (int s = 1; s < 8; s++) {
        float4 v = *(const float4*)(part + (size_t)s * (ROWS * XDBL) + e);
        acc.x += v.x; acc.y += v.y; acc.z += v.z; acc.w += v.w;
    }
    *(float4*)(g_xdbl + e) = acc;
    int col = (int)(e % XDBL);           // 4-aligned; XDBL % 4 == 0
    if (col < DTRANK) {                  // dt activation part -> 3-plane, K=32, K3p=128
        int row = (int)(e / XDBL);
        __nv_bfloat16* dr = g_actb2 + (size_t)row * 128;
        float vv[4] = {acc.x, acc.y, acc.z, acc.w};
#pragma unroll
        for (int j = 0; j < 4; j++) {
            __nv_bfloat16 hi = __float2bfloat16(vv[j]);
            __nv_bfloat16 lo = __float2bfloat16(vv[j] - __bfloat162float(hi));
            dr[col + j] = hi; dr[32 + col + j] = lo; dr[64 + col + j] = hi;
            dr[96 + col + j] = __float2bfloat16(0.f);
        }
    }
}

// ---------------- depthwise causal conv (D_CONV=4) + SiLU; writes u fp32 + split-bf16 ----------------
__global__ void __launch_bounds__(256)
conv_silu_kernel(const float* __restrict__ cw, const float* __restrict__ cb)
{
    int gid = blockIdx.x * 256 + threadIdx.x;   // over ROWS*DIN
    int d = gid & (DIN - 1);
    int row = gid >> 11;
    int t = row & (LL - 1);
    float acc = cb[d];
    const float* base = g_xz + (size_t)row * (2 * DIN) + d;
#pragma unroll
    for (int k = 0; k < DCONV; k++) {
        int off = k - (DCONV - 1);
        if (t + off >= 0)
            acc = fmaf(cw[d * DCONV + k], base[(long)off * (2 * DIN)], acc);
    }
    float s = acc * sigmoidf_(acc);
    g_u[gid] = s;
    split_store3(g_actb, (size_t)row * 6144, d, DIN, s);
}

// ---------------- selective scan v2: warp per (b,d) channel ----------------
#define GD 8
#define CT 32

__global__ void __launch_bounds__(256)
scan_kernel(const float* __restrict__ A_log, const float* __restrict__ Dw)
{
    __shared__ float sB[CT][DSTATE];
    __shared__ float sC[CT][DSTATE];
    __shared__ float sdt[CT][GD];
    __shared__ float su [CT][GD];
    __shared__ float sz [CT][GD];
    __shared__ float sp [GD][CT][33];

    const int tid = threadIdx.x;
    const int w = tid >> 5, lane = tid & 31;
    const int b = blockIdx.y;
    const int d0 = blockIdx.x * GD;
    const int d = d0 + w;

    const float L2E = 1.44269504f;
    const float a0 = -__expf(A_log[d * DSTATE + 2 * lane])     * L2E;
    const float a1 = -__expf(A_log[d * DSTATE + 2 * lane + 1]) * L2E;
    const float Dd = Dw[d];
    float h0 = 0.f, h1 = 0.f;

    const float* xdbl_b = g_xdbl + (size_t)b * LL * XDBL;
    const float* dt_b = g_dt + (size_t)b * LL * DIN + d0;
    const float* u_b  = g_u  + (size_t)b * LL * DIN + d0;
    const float* z_b  = g_xz + (size_t)b * LL * (2 * DIN) + DIN + d0;

    for (int t0 = 0; t0 < LL; t0 += CT) {
        __syncthreads();
#pragma unroll
        for (int r = 0; r < (CT * DSTATE) / 256; r++) {
            int e = tid + r * 256;
            int tt = e >> 6, n = e & 63;
            const float* src = xdbl_b + (size_t)(t0 + tt) * XDBL + DTRANK;
            sB[tt][n] = src[n];
            sC[tt][n] = src[DSTATE + n];
        }
        {
            int tt = tid >> 3, dd = tid & 7;
            sdt[tt][dd] = dt_b[(size_t)(t0 + tt) * DIN + dd];
            su [tt][dd] = u_b [(size_t)(t0 + tt) * DIN + dd];
            sz [tt][dd] = z_b [(size_t)(t0 + tt) * (2 * DIN) + dd];
        }
        __syncthreads();
#pragma unroll 8
        for (int tt = 0; tt < CT; tt++) {
            float dtv = sdt[tt][w], uv = su[tt][w];
            float2 Bv = *(const float2*)&sB[tt][2 * lane];
            float2 Cv = *(const float2*)&sC[tt][2 * lane];
            float dA0 = ex2_(dtv * a0);
            float dA1 = ex2_(dtv * a1);
            float du = dtv * uv;
            h0 = fmaf(dA0, h0, du * Bv.x);
            h1 = fmaf(dA1, h1, du * Bv.y);
            sp[w][tt][lane] = fmaf(h1, Cv.y, h0 * Cv.x);
        }
        __syncwarp();
        {
            const float* pr = &sp[w][lane][0];
            float sum = 0.f;
#pragma unroll
            for (int i = 0; i < 32; i++) sum += pr[i];
            float uvv = su[lane][w];
            float zvv = sz[lane][w];
            float yv = fmaf(uvv, Dd, sum);
            float o = yv * (zvv * sigmoidf_(zvv));
            split_store3(g_actb, (size_t)(b * LL + t0 + lane) * 6144, d, DIN, o);
        }
    }
}

// ---------------- launch ----------------
static inline int cdiv(int a, int b) { return (a + b - 1) / b; }

extern "C" void kernel_launch(void* const* d_in, const int* in_sizes, int n_in,
                              void* d_out, int out_size)
{
    const float* x         = (const float*)d_in[0];
    const float* ln1_g     = (const float*)d_in[1];
    const float* ln1_b     = (const float*)d_in[2];
    const float* in_proj_w = (const float*)d_in[3];
    const float* conv_w    = (const float*)d_in[4];
    const float* conv_b    = (const float*)d_in[5];
    const float* x_proj_w  = (const float*)d_in[6];
    const float* dt_w      = (const float*)d_in[7];
    const float* dt_b      = (const float*)d_in[8];
    const float* A_log     = (const float*)d_in[9];
    const float* D         = (const float*)d_in[10];
    const float* out_proj_w= (const float*)d_in[11];
    const float* ln2_g     = (const float*)d_in[12];
    const float* ln2_b     = (const float*)d_in[13];
    const float* w1        = (const float*)d_in[14];
    const float* b1        = (const float*)d_in[15];
    const float* w2        = (const float*)d_in[16];
    const float* b2        = (const float*)d_in[17];
    float* out = (float*)d_out;

    float *xz, *u, *xdbl, *dt, *x2, *part;
    __nv_bfloat16 *actb, *actb2, *wb;
    cudaGetSymbolAddress((void**)&xz,   g_xz);
    cudaGetSymbolAddress((void**)&u,    g_u);
    cudaGetSymbolAddress((void**)&xdbl, g_xdbl);
    cudaGetSymbolAddress((void**)&dt,   g_dt);
    cudaGetSymbolAddress((void**)&x2,   g_x2);
    cudaGetSymbolAddress((void**)&part, g_part);
    cudaGetSymbolAddress((void**)&actb, g_actb);
    cudaGetSymbolAddress((void**)&actb2,g_actb2);
    cudaGetSymbolAddress((void**)&wb,   g_wb);

    cudaFuncSetAttribute(hmma_gemm,     cudaFuncAttributeMaxDynamicSharedMemorySize, SMEMSZ);
    cudaFuncSetAttribute(hmma_gemmW<0>, cudaFuncAttributeMaxDynamicSharedMemorySize, SMEMSZW);
    cudaFuncSetAttribute(hmma_gemmW<1>, cudaFuncAttributeMaxDynamicSharedMemorySize, SMEMSZW);
    cudaFuncSetAttribute(hmma_gemmW<5>, cudaFuncAttributeMaxDynamicSharedMemorySize, SMEMSZW);

    // 1. LN1 -> actb (split-bf16, K3p=1536)
    ln_kernel<<<ROWS, 128>>>(x, ln1_g, ln1_b, actb, 1e-5f);

    // 2-3. weight conversions (split so launch #4 is the in_proj GEMM for ncu)
    cvt_wip<<<cdiv(N_IP, 256), 256>>>(in_proj_w);
    cvt_wrest<<<cdiv(N_CVTR, 256), 256>>>(x_proj_w, dt_w, out_proj_w, w1, w2);

    // 4. in_proj: xz = y @ in_proj_w^T  [2048 x 4096], K3=1536  (wide)
    hmma_gemmW<0><<<dim3(32, 32, 1), 128, SMEMSZW>>>(actb, wb + OFF_IP, xz, 2 * DIN, 1536, 1536, 0, nullptr);

    // 5. causal conv + silu -> u (fp32) + actb (split-bf16, K3p=6144)
    conv_silu_kernel<<<(ROWS * DIN) / 256, 256>>>(conv_w, conv_b);

    // 6. x_proj: xdbl = u @ x_proj_w^T  [2048 x 160], K3=6144, split-K=8 (narrow)
    hmma_gemm<<<dim3(3, 16, 8), 256, SMEMSZ>>>(actb, wb + OFF_XP, part, XDBL, 6144, 768,
                                               (size_t)ROWS * XDBL);
    // 7. reduce x_proj + fused dt-activation conversion -> xdbl + actb2
    reduce_xp<<<(ROWS * XDBL / 4 + 255) / 256, 256>>>();

    // 8. dt = softplus(xdbl[:, :32] @ dt_w^T + dt_b)  [2048 x 2048], K3p=128 (wide)
    hmma_gemmW<1><<<dim3(16, 32, 1), 128, SMEMSZW>>>(actb2, wb + OFF_DT, dt, DIN, 128, 128, 0, dt_b);

    // 9. selective scan -> actb (split-bf16, K3p=6144)
    scan_kernel<<<dim3(DIN / GD, BB), 256>>>(A_log, D);

    // 10. out_proj: x2 = x + ys @ out_proj_w^T  [2048 x 512], K3=6144, split-K=3 (wide)
    hmma_gemmW<0><<<dim3(4, 32, 3), 128, SMEMSZW>>>(actb, wb + OFF_OP, part, DIM, 6144, 2048,
                                                    (size_t)ROWS * DIM, nullptr);
    reduce_kernel<2><<<(ROWS * DIM / 4 + 255) / 256, 256>>>(part, x2, ROWS * DIM / 4, 3,
                                                            (size_t)ROWS * DIM, DIM, nullptr, x);

    // 11. LN2 -> actb (split-bf16, K3p=1536)
    ln_kernel<<<ROWS, 128>>>(x2, ln2_g, ln2_b, actb, 1e-6f);

    // 12. h1 = gelu(y2 @ w1^T + b1) -> actb2 (split-bf16, K3p=6144)  [2048 x 2048], K3=1536 (wide)
    hmma_gemmW<5><<<dim3(16, 32, 1), 128, SMEMSZW>>>(actb, wb + OFF_W1, nullptr, 4 * DIM, 1536, 1536, 0, b1);

    // 13. out = x2 + h1 @ w2^T + b2  [2048 x 512], K3=6144, split-K=3 (wide)
    hmma_gemmW<0><<<dim3(4, 32, 3), 128, SMEMSZW>>>(actb2, wb + OFF_W2, part, DIM, 6144, 2048,
                                                    (size_t)ROWS * DIM, nullptr);
    reduce_kernel<4><<<(ROWS * DIM / 4 + 255) / 256, 256>>>(part, out, ROWS * DIM / 4, 3,
                                                            (size_t)ROWS * DIM, DIM, b2, x2);
}